// round 8
// baseline (speedup 1.0000x reference)
#include <cuda_runtime.h>
#include <cuda_bf16.h>
#include <cstdint>
#include <math.h>

// ---------------- scratch (static device globals; no allocation) ----------
__device__ float g_Q[4096 * 2048];      // Q fp32, reused for attention-out O
__device__ float g_K[4096 * 2048];
__device__ float g_V[4096 * 2048];
__device__ int8_t g_X1[4096 * 2048];    // activation int8 hi limb
__device__ int8_t g_X0[4096 * 2048];    // activation int8 lo limb
__device__ int8_t g_W1[2048 * 2048];
__device__ int8_t g_W0[2048 * 2048];
__device__ float  g_aX[4096];
__device__ float  g_aW[2048];
__device__ __nv_bfloat16 g_Qhi[4096 * 2048];
__device__ __nv_bfloat16 g_Qlo[4096 * 2048];
__device__ __nv_bfloat16 g_Khi[4096 * 2048];
__device__ __nv_bfloat16 g_Klo[4096 * 2048];
__device__ __nv_bfloat16 g_VThi[2048 * 4096];   // [h*128+d][s]
__device__ __nv_bfloat16 g_VTlo[2048 * 4096];

// ======================= portable PTX helpers (sm_80+) =====================
__device__ __forceinline__ uint32_t smem_u32(const void* p) {
    uint32_t a;
    asm("{ .reg .u64 t; cvta.to.shared.u64 t, %1; cvt.u32.u64 %0, t; }"
        : "=r"(a) : "l"(p));
    return a;
}
#define CP_ASYNC16(dst, src) \
    asm volatile("cp.async.cg.shared.global [%0], [%1], 16;" \
                 :: "r"(dst), "l"(src))
#define CP_COMMIT() asm volatile("cp.async.commit_group;")
#define CP_WAIT1()  asm volatile("cp.async.wait_group 1;")
#define CP_WAIT0()  asm volatile("cp.async.wait_group 0;")
#define LDSM_X4(r, addr) \
    asm volatile("ldmatrix.sync.aligned.m8n8.x4.shared.b16 {%0,%1,%2,%3}, [%4];" \
                 : "=r"((r)[0]), "=r"((r)[1]), "=r"((r)[2]), "=r"((r)[3]) \
                 : "r"(addr))
#define MMA16816(d, a, b0, b1) \
    asm volatile("mma.sync.aligned.m16n8k16.row.col.f32.bf16.bf16.f32 " \
                 "{%0,%1,%2,%3}, {%4,%5,%6,%7}, {%8,%9}, {%0,%1,%2,%3};" \
                 : "+f"((d)[0]), "+f"((d)[1]), "+f"((d)[2]), "+f"((d)[3]) \
                 : "r"((a)[0]), "r"((a)[1]), "r"((a)[2]), "r"((a)[3]), \
                   "r"(b0), "r"(b1))
#define MMAS8(d, a, b0, b1) \
    asm volatile("mma.sync.aligned.m16n8k32.row.col.s32.s8.s8.s32 " \
                 "{%0,%1,%2,%3}, {%4,%5,%6,%7}, {%8,%9}, {%0,%1,%2,%3};" \
                 : "+r"((d)[0]), "+r"((d)[1]), "+r"((d)[2]), "+r"((d)[3]) \
                 : "r"((a)[0]), "r"((a)[1]), "r"((a)[2]), "r"((a)[3]), \
                   "r"(b0), "r"(b1))
__device__ __forceinline__ float ex2(float x) {
    float r;
    asm("ex2.approx.f32 %0, %1;" : "=f"(r) : "f"(x));
    return r;
}

// ---------------------------------------------------------------------------
// quantize rows: fp32 [rows][2048] -> int8 2-limb (a = alpha*(128*a1+a0))
// one block per row, 256 threads x 8 elements.
// ---------------------------------------------------------------------------
__global__ void __launch_bounds__(256) quant_rows(
    const float* __restrict__ in, int8_t* __restrict__ q1,
    int8_t* __restrict__ q0, float* __restrict__ alpha) {
    __shared__ float red[8];
    const int r = blockIdx.x;
    const int t = threadIdx.x;
    const int lane = t & 31;
    const int wid = t >> 5;
    const float* row = in + (size_t)r * 2048;

    float4 v0 = ((const float4*)row)[t * 2];
    float4 v1 = ((const float4*)row)[t * 2 + 1];
    float f[8] = {v0.x, v0.y, v0.z, v0.w, v1.x, v1.y, v1.z, v1.w};

    float mx = 0.f;
#pragma unroll
    for (int i = 0; i < 8; i++) mx = fmaxf(mx, fabsf(f[i]));
#pragma unroll
    for (int off = 16; off > 0; off >>= 1)
        mx = fmaxf(mx, __shfl_xor_sync(0xffffffffu, mx, off));
    if (lane == 0) red[wid] = mx;
    __syncthreads();
    mx = red[0];
#pragma unroll
    for (int i = 1; i < 8; i++) mx = fmaxf(mx, red[i]);
    mx = fmaxf(mx, 1e-20f);

    if (t == 0) alpha[r] = mx * (1.0f / 16256.0f);
    const float inv = 16256.0f / mx;

    uint32_t p1[2] = {0, 0}, p0[2] = {0, 0};
#pragma unroll
    for (int i = 0; i < 8; i++) {
        int qi = __float2int_rn(f[i] * inv);
        qi = max(-16256, min(16256, qi));
        int a1 = ((qi + 64 + 16384) >> 7) - 128;   // in [-127,127]
        int a0 = qi - (a1 << 7);                   // in [-64,64)
        p1[i >> 2] |= (uint32_t)(a1 & 0xff) << ((i & 3) * 8);
        p0[i >> 2] |= (uint32_t)(a0 & 0xff) << ((i & 3) * 8);
    }
    size_t base = ((size_t)r * 2048 + t * 8) >> 3;   // int2 index
    ((uint2*)q1)[base] = make_uint2(p1[0], p1[1]);
    ((uint2*)q0)[base] = make_uint2(p0[0], p0[1]);
}

// ---------------------------------------------------------------------------
// fused per-(token,head) RMSNorm + scale + bf16 hi/lo split (one warp / row)
// ---------------------------------------------------------------------------
__global__ void __launch_bounds__(256) rmsnorm_split(
    const float* __restrict__ X, const float* __restrict__ w,
    __nv_bfloat16* __restrict__ hi, __nv_bfloat16* __restrict__ lo,
    int nrows, float scale) {
    int warp = (blockIdx.x * blockDim.x + threadIdx.x) >> 5;
    int lane = threadIdx.x & 31;
    if (warp >= nrows) return;

    float4 v = *(const float4*)&X[(size_t)warp * 128 + (lane << 2)];
    float ss = v.x * v.x + v.y * v.y + v.z * v.z + v.w * v.w;
#pragma unroll
    for (int off = 16; off > 0; off >>= 1)
        ss += __shfl_xor_sync(0xffffffffu, ss, off);

    float inv = rsqrtf(ss * (1.0f / 128.0f) + 1e-6f) * scale;
    float4 wv = *(const float4*)&w[lane << 2];
    v.x *= inv * wv.x; v.y *= inv * wv.y;
    v.z *= inv * wv.z; v.w *= inv * wv.w;

    union { __nv_bfloat16 b[4]; uint2 u; } H, L;
    H.b[0] = __float2bfloat16(v.x);
    H.b[1] = __float2bfloat16(v.y);
    H.b[2] = __float2bfloat16(v.z);
    H.b[3] = __float2bfloat16(v.w);
    L.b[0] = __float2bfloat16(v.x - __bfloat162float(H.b[0]));
    L.b[1] = __float2bfloat16(v.y - __bfloat162float(H.b[1]));
    L.b[2] = __float2bfloat16(v.z - __bfloat162float(H.b[2]));
    L.b[3] = __float2bfloat16(v.w - __bfloat162float(H.b[3]));
    size_t o = (size_t)warp * 32 + lane;
    ((uint2*)hi)[o] = H.u;
    ((uint2*)lo)[o] = L.u;
}

// ---------------------------------------------------------------------------
// transpose + split V: in [4096][2048] fp32 -> VT hi/lo [2048][4096] bf16
// ---------------------------------------------------------------------------
__global__ void __launch_bounds__(256) transpose_split(
    const float* __restrict__ in, __nv_bfloat16* __restrict__ thi,
    __nv_bfloat16* __restrict__ tlo) {
    __shared__ float t[32][33];
    const int s0 = blockIdx.x << 5;
    const int c0 = blockIdx.y << 5;
    const int tx = threadIdx.x & 31;
    const int ty = threadIdx.x >> 5;
#pragma unroll
    for (int i = 0; i < 4; i++) {
        int r = (ty << 2) + i;
        t[r][tx] = in[(size_t)(s0 + r) * 2048 + c0 + tx];
    }
    __syncthreads();
#pragma unroll
    for (int i = 0; i < 4; i++) {
        int r = (ty << 2) + i;
        float v = t[tx][r];
        __nv_bfloat16 h = __float2bfloat16(v);
        __nv_bfloat16 l = __float2bfloat16(v - __bfloat162float(h));
        size_t o = (size_t)(c0 + r) * 4096 + s0 + tx;
        thi[o] = h;
        tlo[o] = l;
    }
}

// ---------------------------------------------------------------------------
// int8 2-limb GEMM: C[4096,2048] = A[4096,2048] * B[2048,2048]^T,
// a = aA[r]*(128*a1+a0), b = aB[c]*(128*b1+b0);
// C = aA*aB*(16384*S11 + 128*(S10+S01))   [a0*b0 term dropped, ~6e-5 rel]
// CTA 128x128, 8 warps (warp 64x32), K chunk 32 (1 x k32 MMA), 3 MMAs/chunk,
// two s32 accumulator sets (no overflow over K=2048), 3-stage cp.async.
// 32B-row swizzle: 16B chunk c -> c ^ ((row>>2)&1)   [conflict-free ldmatrix]
// ---------------------------------------------------------------------------
#define S8S      16384              // stage: 4 tiles x 4KB
#define S8_SMEM  (3 * S8S)          // 49152

__global__ void __launch_bounds__(256, 1) gemm_s8(
    const int8_t* __restrict__ A1, const int8_t* __restrict__ A0,
    const int8_t* __restrict__ B1, const int8_t* __restrict__ B0,
    const float* __restrict__ aA, const float* __restrict__ aB,
    float* __restrict__ C) {
    constexpr int Nd = 2048, Kd = 2048;
    extern __shared__ char smem[];
    const uint32_t sbase = smem_u32(smem);
    const int tid = threadIdx.x;
    const int lane = tid & 31;
    const int wid = tid >> 5;
    const int m0 = blockIdx.y << 7;
    const int n0 = blockIdx.x << 7;
    const int wm = (wid & 1) << 6;       // 0/64
    const int wn = (wid >> 1) << 5;      // 0/32/64/96

    int acc1[4][4][4], accX[4][4][4];
#pragma unroll
    for (int mi = 0; mi < 4; mi++)
#pragma unroll
        for (int ni = 0; ni < 4; ni++)
#pragma unroll
            for (int q = 0; q < 4; q++) { acc1[mi][ni][q] = 0; accX[mi][ni][q] = 0; }

    const int lr = tid >> 1;             // row 0..127
    const int lc = tid & 1;              // 16B chunk 0/1

    auto issue = [&](int it, int stage) {
        int kk = it << 5;                // 32 int8 per chunk
        size_t ga = (size_t)(m0 + lr) * Kd + kk + lc * 16;
        size_t gb = (size_t)(n0 + lr) * Kd + kk + lc * 16;
        uint32_t st = sbase + stage * S8S + lr * 32 +
                      (uint32_t)((lc ^ ((lr >> 2) & 1)) << 4);
        CP_ASYNC16(st,          A1 + ga);
        CP_ASYNC16(st + 4096,   A0 + ga);
        CP_ASYNC16(st + 8192,   B1 + gb);
        CP_ASYNC16(st + 12288,  B0 + gb);
    };

    issue(0, 0); CP_COMMIT();
    issue(1, 1); CP_COMMIT();

    constexpr int NITER = 64;            // 2048 / 32
    int stage = 0, nstage = 2;
    for (int it = 0; it < NITER; it++) {
        if (it < NITER - 1) CP_WAIT1(); else CP_WAIT0();
        __syncthreads();
        if (it + 2 < NITER) { issue(it + 2, nstage); CP_COMMIT(); }

        const uint32_t sA1 = sbase + stage * S8S;
        const uint32_t sA0 = sA1 + 4096;
        const uint32_t sB1 = sA1 + 8192;
        const uint32_t sB0 = sA1 + 12288;

        uint32_t b1f[2][4], b0f[2][4];
#pragma unroll
        for (int pr = 0; pr < 2; pr++) {
            int row = wn + pr * 16 + (lane & 7) + (((lane >> 4) & 1) << 3);
            int cb = (lane >> 3) & 1;
            uint32_t off = (uint32_t)(row * 32 + ((cb ^ ((row >> 2) & 1)) << 4));
            LDSM_X4(b1f[pr], sB1 + off);
            LDSM_X4(b0f[pr], sB0 + off);
        }
#pragma unroll
        for (int mi = 0; mi < 4; mi++) {
            uint32_t a1f[4], a0f[4];
            int row = wm + mi * 16 + (lane & 15);
            int cb = lane >> 4;
            uint32_t off = (uint32_t)(row * 32 + ((cb ^ ((row >> 2) & 1)) << 4));
            LDSM_X4(a1f, sA1 + off);
            LDSM_X4(a0f, sA0 + off);
#pragma unroll
            for (int ni = 0; ni < 4; ni++) {
                int pr = ni >> 1, o2 = (ni & 1) << 1;
                MMAS8(acc1[mi][ni], a1f, b1f[pr][o2], b1f[pr][o2 + 1]);
                MMAS8(accX[mi][ni], a1f, b0f[pr][o2], b0f[pr][o2 + 1]);
                MMAS8(accX[mi][ni], a0f, b1f[pr][o2], b1f[pr][o2 + 1]);
            }
        }
        stage = (stage == 2) ? 0 : stage + 1;
        nstage = (nstage == 2) ? 0 : nstage + 1;
    }

    // epilogue: dequantize
#pragma unroll
    for (int mi = 0; mi < 4; mi++) {
        int r0 = m0 + wm + mi * 16 + (lane >> 2);
        float sa0 = aA[r0], sa1 = aA[r0 + 8];
#pragma unroll
        for (int ni = 0; ni < 4; ni++) {
            int cc = n0 + wn + ni * 8 + ((lane & 3) << 1);
            float sb0 = aB[cc], sb1 = aB[cc + 1];
            float f0 = fmaf(16384.f, __int2float_rn(acc1[mi][ni][0]),
                            128.f * __int2float_rn(accX[mi][ni][0]));
            float f1 = fmaf(16384.f, __int2float_rn(acc1[mi][ni][1]),
                            128.f * __int2float_rn(accX[mi][ni][1]));
            float f2 = fmaf(16384.f, __int2float_rn(acc1[mi][ni][2]),
                            128.f * __int2float_rn(accX[mi][ni][2]));
            float f3 = fmaf(16384.f, __int2float_rn(acc1[mi][ni][3]),
                            128.f * __int2float_rn(accX[mi][ni][3]));
            *(float2*)&C[(size_t)r0 * Nd + cc] =
                make_float2(f0 * sa0 * sb0, f1 * sa0 * sb1);
            *(float2*)&C[(size_t)(r0 + 8) * Nd + cc] =
                make_float2(f2 * sa1 * sb0, f3 * sa1 * sb1);
        }
    }
}

// ---------------------------------------------------------------------------
// Flash attention, mma.sync bf16 hi/lo (3-pass). 128 queries x one head per
// CTA, 8 warps. K tiles of 64, 2-stage cp.async, ONE sync per tile.
// Epilogue writes fp32 O (feeds quantizer for the O-projection).
// ---------------------------------------------------------------------------
#define FM_QHI   0
#define FM_QLO   32768
#define FM_STG0  65536
#define FM_STAGE 65536               // Khi | Klo | Vhi | Vlo @ 16KB each
#define FM_SMEM  (65536 + 2 * FM_STAGE)   // 196608

__device__ __forceinline__ uint32_t sw256(int row, int kb) {
    return (uint32_t)(row * 256 + ((kb & 0x80) | ((kb ^ ((row & 7) << 4)) & 0x70)));
}

__global__ void __launch_bounds__(256, 1) flash_mma(
    const __nv_bfloat16* __restrict__ Qhi, const __nv_bfloat16* __restrict__ Qlo,
    const __nv_bfloat16* __restrict__ Khi, const __nv_bfloat16* __restrict__ Klo,
    const __nv_bfloat16* __restrict__ VThi, const __nv_bfloat16* __restrict__ VTlo,
    float* __restrict__ Og) {
    extern __shared__ char smem[];
    const uint32_t sb = smem_u32(smem);
    const int tid = threadIdx.x;
    const int lane = tid & 31;
    const int wid = tid >> 5;
    const int h = blockIdx.y;
    const int m0 = blockIdx.x << 7;
    const int hoff = h << 7;
    const int qbase = wid << 4;

    // ---- load Q tiles (hi/lo) ----
    {
        int row = tid >> 1;
        int c0 = (tid & 1) << 3;
        const __nv_bfloat16* qh = Qhi + (size_t)(m0 + row) * 2048 + hoff;
        const __nv_bfloat16* ql = Qlo + (size_t)(m0 + row) * 2048 + hoff;
#pragma unroll
        for (int j = 0; j < 8; j++) {
            int c = c0 + j;
            uint32_t sw = sw256(row, c << 4);
            CP_ASYNC16(sb + FM_QHI + sw, qh + c * 8);
            CP_ASYNC16(sb + FM_QLO + sw, ql + c * 8);
        }
    }

    const int krow = tid >> 2;
    const int kc0 = (tid & 3) << 2;
    const int vrow = tid >> 1;
    const int vc0 = (tid & 1) << 2;

#define FM_ISSUE(kt, buf) do {                                                  \
    uint32_t _st = sb + FM_STG0 + (buf) * FM_STAGE;                             \
    const __nv_bfloat16* _kh = Khi + (size_t)((kt) + krow) * 2048 + hoff;       \
    const __nv_bfloat16* _kl = Klo + (size_t)((kt) + krow) * 2048 + hoff;       \
    _Pragma("unroll")                                                           \
    for (int _j = 0; _j < 4; _j++) {                                            \
        int _c = kc0 + _j;                                                      \
        uint32_t _sw = sw256(krow, _c << 4);                                    \
        CP_ASYNC16(_st + _sw, _kh + _c * 8);                                    \
        CP_ASYNC16(_st + 16384 + _sw, _kl + _c * 8);                            \
    }                                                                           \
    const __nv_bfloat16* _vh = VThi + (size_t)(hoff + vrow) * 4096 + (kt);      \
    const __nv_bfloat16* _vl = VTlo + (size_t)(hoff + vrow) * 4096 + (kt);      \
    _Pragma("unroll")                                                           \
    for (int _j = 0; _j < 4; _j++) {                                            \
        int _c = vc0 + _j;                                                      \
        uint32_t _sw = (uint32_t)(vrow * 128 + ((_c << 4) ^ ((vrow & 7) << 4)));\
        CP_ASYNC16(_st + 32768 + _sw, _vh + _c * 8);                            \
        CP_ASYNC16(_st + 49152 + _sw, _vl + _c * 8);                            \
    }                                                                           \
} while (0)

    FM_ISSUE(0, 0);
    CP_COMMIT();

    float m0s = -1e30f, m1s = -1e30f, l0 = 0.f, l1 = 0.f;
    float o[16][4];
#pragma unroll
    for (int j = 0; j < 16; j++)
#pragma unroll
        for (int q = 0; q < 4; q++) o[j][q] = 0.f;

    const int NITER = 4096 / 64;
    for (int it = 0; it < NITER; it++) {
        const int buf = it & 1;
        CP_WAIT0();
        __syncthreads();
        if (it + 1 < NITER) {
            FM_ISSUE((it + 1) << 6, buf ^ 1);
            CP_COMMIT();
        }

        const uint32_t sKh = sb + FM_STG0 + buf * FM_STAGE;
        const uint32_t sKl = sKh + 16384;
        const uint32_t sVh = sKh + 32768;
        const uint32_t sVl = sKh + 49152;

        // ---- S = Q K^T (3-pass) ----
        float s[8][4];
#pragma unroll
        for (int j = 0; j < 8; j++)
#pragma unroll
            for (int q = 0; q < 4; q++) s[j][q] = 0.f;

#pragma unroll
        for (int ks = 0; ks < 8; ks++) {
            uint32_t ah[4], al[4], bh[4][4], bl[4][4];
            {
                int row = qbase + (lane & 15);
                int kb = ks * 32 + ((lane >> 4) << 4);
                LDSM_X4(ah, sb + FM_QHI + sw256(row, kb));
                LDSM_X4(al, sb + FM_QLO + sw256(row, kb));
            }
#pragma unroll
            for (int pr = 0; pr < 4; pr++) {
                int row = pr * 16 + (lane & 7) + (((lane >> 4) & 1) << 3);
                int kb = ks * 32 + (((lane >> 3) & 1) << 4);
                uint32_t sw = sw256(row, kb);
                LDSM_X4(bh[pr], sKh + sw);
                LDSM_X4(bl[pr], sKl + sw);
            }
#pragma unroll
            for (int j = 0; j < 8; j++) {
                int pr = j >> 1, o2 = (j & 1) << 1;
                MMA16816(s[j], ah, bh[pr][o2], bh[pr][o2 + 1]);
                MMA16816(s[j], ah, bl[pr][o2], bl[pr][o2 + 1]);
                MMA16816(s[j], al, bh[pr][o2], bh[pr][o2 + 1]);
            }
        }

        // ---- online softmax (base-2) ----
        float mx0 = -1e30f, mx1 = -1e30f;
#pragma unroll
        for (int j = 0; j < 8; j++) {
            mx0 = fmaxf(mx0, fmaxf(s[j][0], s[j][1]));
            mx1 = fmaxf(mx1, fmaxf(s[j][2], s[j][3]));
        }
        mx0 = fmaxf(mx0, __shfl_xor_sync(0xffffffffu, mx0, 1));
        mx0 = fmaxf(mx0, __shfl_xor_sync(0xffffffffu, mx0, 2));
        mx1 = fmaxf(mx1, __shfl_xor_sync(0xffffffffu, mx1, 1));
        mx1 = fmaxf(mx1, __shfl_xor_sync(0xffffffffu, mx1, 2));
        float mn0 = fmaxf(m0s, mx0), mn1 = fmaxf(m1s, mx1);
        float corr0 = ex2(m0s - mn0), corr1 = ex2(m1s - mn1);
        m0s = mn0; m1s = mn1;

        float sum0 = 0.f, sum1 = 0.f;
        float p[8][4];
#pragma unroll
        for (int j = 0; j < 8; j++) {
            p[j][0] = ex2(s[j][0] - mn0);
            p[j][1] = ex2(s[j][1] - mn0);
            p[j][2] = ex2(s[j][2] - mn1);
            p[j][3] = ex2(s[j][3] - mn1);
            sum0 += p[j][0] + p[j][1];
            sum1 += p[j][2] + p[j][3];
        }
        sum0 += __shfl_xor_sync(0xffffffffu, sum0, 1);
        sum0 += __shfl_xor_sync(0xffffffffu, sum0, 2);
        sum1 += __shfl_xor_sync(0xffffffffu, sum1, 1);
        sum1 += __shfl_xor_sync(0xffffffffu, sum1, 2);
        l0 = l0 * corr0 + sum0;
        l1 = l1 * corr1 + sum1;

        // pack P -> bf16 hi/lo A-fragments
        uint32_t pahi[4][4], palo[4][4];
#pragma unroll
        for (int kt = 0; kt < 4; kt++) {
#pragma unroll
            for (int t = 0; t < 2; t++) {
                int j = 2 * kt + t;
#pragma unroll
                for (int half = 0; half < 2; half++) {
                    float f0 = p[j][half * 2], f1 = p[j][half * 2 + 1];
                    __nv_bfloat162 hh = __floats2bfloat162_rn(f0, f1);
                    float r0 = f0 - __low2float(hh);
                    float r1 = f1 - __high2float(hh);
                    __nv_bfloat162 ll = __floats2bfloat162_rn(r0, r1);
                    pahi[kt][t * 2 + half] = *(uint32_t*)&hh;
                    palo[kt][t * 2 + half] = *(uint32_t*)&ll;
                }
            }
        }

#pragma unroll
        for (int j = 0; j < 16; j++) {
            o[j][0] *= corr0; o[j][1] *= corr0;
            o[j][2] *= corr1; o[j][3] *= corr1;
        }

        // ---- O += P V (3-pass) ----
#pragma unroll
        for (int kt = 0; kt < 4; kt++) {
#pragma unroll
            for (int pr = 0; pr < 8; pr++) {
                uint32_t bvh[4], bvl[4];
                int row = pr * 16 + (lane & 7) + (((lane >> 4) & 1) << 3);
                int kb = kt * 32 + (((lane >> 3) & 1) << 4);
                uint32_t sw = (uint32_t)(row * 128 + (kb ^ ((row & 7) << 4)));
                LDSM_X4(bvh, sVh + sw);
                LDSM_X4(bvl, sVl + sw);
#pragma unroll
                for (int t = 0; t < 2; t++) {
                    int j = pr * 2 + t;
                    int o2 = t << 1;
                    MMA16816(o[j], pahi[kt], bvh[o2], bvh[o2 + 1]);
                    MMA16816(o[j], pahi[kt], bvl[o2], bvl[o2 + 1]);
                    MMA16816(o[j], palo[kt], bvh[o2], bvh[o2 + 1]);
                }
            }
        }
    }

    // ---- epilogue: fp32 O ----
    float inv0 = 1.0f / l0, inv1 = 1.0f / l1;
    int r0 = m0 + qbase + (lane >> 2);
#pragma unroll
    for (int j = 0; j < 16; j++) {
        int cc = hoff + j * 8 + ((lane & 3) << 1);
        *(float2*)&Og[(size_t)r0 * 2048 + cc] =
            make_float2(o[j][0] * inv0, o[j][1] * inv0);
        *(float2*)&Og[(size_t)(r0 + 8) * 2048 + cc] =
            make_float2(o[j][2] * inv1, o[j][3] * inv1);
    }
}

// ---------------------------------------------------------------------------
// Launch
// ---------------------------------------------------------------------------
extern "C" void kernel_launch(void* const* d_in, const int* in_sizes, int n_in,
                              void* d_out, int out_size) {
    const float* x  = (const float*)d_in[0];
    const float* wq = (const float*)d_in[1];
    const float* wk = (const float*)d_in[2];
    const float* wv = (const float*)d_in[3];
    const float* wo = (const float*)d_in[4];
    const float* qn = (const float*)d_in[5];
    const float* kn = (const float*)d_in[6];
    float* out = (float*)d_out;

    void *pq, *pk, *pv, *px1, *px0, *pw1, *pw0, *pax, *paw;
    void *pqh, *pql, *pkh, *pkl, *pvh, *pvl;
    cudaGetSymbolAddress(&pq, g_Q);
    cudaGetSymbolAddress(&pk, g_K);
    cudaGetSymbolAddress(&pv, g_V);
    cudaGetSymbolAddress(&px1, g_X1);
    cudaGetSymbolAddress(&px0, g_X0);
    cudaGetSymbolAddress(&pw1, g_W1);
    cudaGetSymbolAddress(&pw0, g_W0);
    cudaGetSymbolAddress(&pax, g_aX);
    cudaGetSymbolAddress(&paw, g_aW);
    cudaGetSymbolAddress(&pqh, g_Qhi);
    cudaGetSymbolAddress(&pql, g_Qlo);
    cudaGetSymbolAddress(&pkh, g_Khi);
    cudaGetSymbolAddress(&pkl, g_Klo);
    cudaGetSymbolAddress(&pvh, g_VThi);
    cudaGetSymbolAddress(&pvl, g_VTlo);
    float* Q = (float*)pq;
    float* K = (float*)pk;
    float* V = (float*)pv;
    int8_t* X1 = (int8_t*)px1;
    int8_t* X0 = (int8_t*)px0;
    int8_t* W1 = (int8_t*)pw1;
    int8_t* W0 = (int8_t*)pw0;
    float* aX = (float*)pax;
    float* aW = (float*)paw;

    cudaFuncSetAttribute(gemm_s8, cudaFuncAttributeMaxDynamicSharedMemorySize, S8_SMEM);
    cudaFuncSetAttribute(flash_mma, cudaFuncAttributeMaxDynamicSharedMemorySize, FM_SMEM);

    const int M = 4096, D = 2048;
    dim3 gg(D / 128, M / 128);      // (16, 32)

    quant_rows<<<M, 256>>>(x, X1, X0, aX);

    quant_rows<<<D, 256>>>(wq, W1, W0, aW);
    gemm_s8<<<gg, 256, S8_SMEM>>>(X1, X0, W1, W0, aX, aW, Q);

    quant_rows<<<D, 256>>>(wk, W1, W0, aW);
    gemm_s8<<<gg, 256, S8_SMEM>>>(X1, X0, W1, W0, aX, aW, K);

    quant_rows<<<D, 256>>>(wv, W1, W0, aW);
    gemm_s8<<<gg, 256, S8_SMEM>>>(X1, X0, W1, W0, aX, aW, V);

    // fused rmsnorm + scale + bf16 split (qscale = 1/sqrt(128) * log2(e))
    const float qscale = 0.08838834764831845f * 1.4426950408889634f;
    int nrows = M * 16;
    rmsnorm_split<<<nrows / 8, 256>>>(Q, qn, (__nv_bfloat16*)pqh,
                                      (__nv_bfloat16*)pql, nrows, qscale);
    rmsnorm_split<<<nrows / 8, 256>>>(K, kn, (__nv_bfloat16*)pkh,
                                      (__nv_bfloat16*)pkl, nrows, 1.0f);
    transpose_split<<<dim3(M / 32, D / 32), 256>>>(V, (__nv_bfloat16*)pvh,
                                                   (__nv_bfloat16*)pvl);

    // flash writes fp32 O into g_Q (free after rmsnorm_split)
    flash_mma<<<dim3(M / 128, 16), 256, FM_SMEM>>>(
        (__nv_bfloat16*)pqh, (__nv_bfloat16*)pql,
        (__nv_bfloat16*)pkh, (__nv_bfloat16*)pkl,
        (__nv_bfloat16*)pvh, (__nv_bfloat16*)pvl, Q);

    // O-projection (int8)
    quant_rows<<<M, 256>>>(Q, X1, X0, aX);
    quant_rows<<<D, 256>>>(wo, W1, W0, aW);
    gemm_s8<<<gg, 256, S8_SMEM>>>(X1, X0, W1, W0, aX, aW, out);
}

// round 9
// speedup vs baseline: 1.8800x; 1.8800x over previous
#include <cuda_runtime.h>
#include <cuda_bf16.h>
#include <cstdint>
#include <math.h>

// ---------------- scratch (static device globals; no allocation) ----------
__device__ float g_Q[4096 * 2048];
__device__ float g_K[4096 * 2048];
__device__ float g_V[4096 * 2048];
__device__ __nv_bfloat16 g_Xhi[4096 * 2048];
__device__ __nv_bfloat16 g_Xlo[4096 * 2048];
__device__ __nv_bfloat16 g_Whi[2048 * 2048];
__device__ __nv_bfloat16 g_Wlo[2048 * 2048];
__device__ __nv_bfloat16 g_Qhi[4096 * 2048];
__device__ __nv_bfloat16 g_Qlo[4096 * 2048];
__device__ __nv_bfloat16 g_Khi[4096 * 2048];
__device__ __nv_bfloat16 g_Klo[4096 * 2048];
__device__ __nv_bfloat16 g_VThi[2048 * 4096];   // [h*128+d][s]
__device__ __nv_bfloat16 g_VTlo[2048 * 4096];

// ======================= portable PTX helpers (sm_80+) =====================
__device__ __forceinline__ uint32_t smem_u32(const void* p) {
    uint32_t a;
    asm("{ .reg .u64 t; cvta.to.shared.u64 t, %1; cvt.u32.u64 %0, t; }"
        : "=r"(a) : "l"(p));
    return a;
}
#define CP_ASYNC16(dst, src) \
    asm volatile("cp.async.cg.shared.global [%0], [%1], 16;" \
                 :: "r"(dst), "l"(src))
#define CP_COMMIT() asm volatile("cp.async.commit_group;")
#define CP_WAIT1()  asm volatile("cp.async.wait_group 1;")
#define CP_WAIT0()  asm volatile("cp.async.wait_group 0;")
#define LDSM_X4(r, addr) \
    asm volatile("ldmatrix.sync.aligned.m8n8.x4.shared.b16 {%0,%1,%2,%3}, [%4];" \
                 : "=r"((r)[0]), "=r"((r)[1]), "=r"((r)[2]), "=r"((r)[3]) \
                 : "r"(addr))
#define MMA16816(d, a, b0, b1) \
    asm volatile("mma.sync.aligned.m16n8k16.row.col.f32.bf16.bf16.f32 " \
                 "{%0,%1,%2,%3}, {%4,%5,%6,%7}, {%8,%9}, {%0,%1,%2,%3};" \
                 : "+f"((d)[0]), "+f"((d)[1]), "+f"((d)[2]), "+f"((d)[3]) \
                 : "r"((a)[0]), "r"((a)[1]), "r"((a)[2]), "r"((a)[3]), \
                   "r"(b0), "r"(b1))
__device__ __forceinline__ float ex2(float x) {
    float r;
    asm("ex2.approx.f32 %0, %1;" : "=f"(r) : "f"(x));
    return r;
}

// ---------------------------------------------------------------------------
// split fp32 -> bf16 hi + bf16 lo (scale folded in)
// ---------------------------------------------------------------------------
__global__ void __launch_bounds__(256) split_bf16(const float* __restrict__ in,
                                                  __nv_bfloat16* __restrict__ hi,
                                                  __nv_bfloat16* __restrict__ lo,
                                                  int n4, float scale) {
    int i = blockIdx.x * blockDim.x + threadIdx.x;
    if (i >= n4) return;
    float4 v = ((const float4*)in)[i];
    v.x *= scale; v.y *= scale; v.z *= scale; v.w *= scale;
    union { __nv_bfloat16 b[4]; uint2 u; } H, L;
    H.b[0] = __float2bfloat16(v.x);
    H.b[1] = __float2bfloat16(v.y);
    H.b[2] = __float2bfloat16(v.z);
    H.b[3] = __float2bfloat16(v.w);
    L.b[0] = __float2bfloat16(v.x - __bfloat162float(H.b[0]));
    L.b[1] = __float2bfloat16(v.y - __bfloat162float(H.b[1]));
    L.b[2] = __float2bfloat16(v.z - __bfloat162float(H.b[2]));
    L.b[3] = __float2bfloat16(v.w - __bfloat162float(H.b[3]));
    ((uint2*)hi)[i] = H.u;
    ((uint2*)lo)[i] = L.u;
}

// ---------------------------------------------------------------------------
// fused per-(token,head) RMSNorm + scale + bf16 hi/lo split (one warp / row)
// ---------------------------------------------------------------------------
__global__ void __launch_bounds__(256) rmsnorm_split(
    const float* __restrict__ X, const float* __restrict__ w,
    __nv_bfloat16* __restrict__ hi, __nv_bfloat16* __restrict__ lo,
    int nrows, float scale) {
    int warp = (blockIdx.x * blockDim.x + threadIdx.x) >> 5;
    int lane = threadIdx.x & 31;
    if (warp >= nrows) return;

    float4 v = *(const float4*)&X[(size_t)warp * 128 + (lane << 2)];
    float ss = v.x * v.x + v.y * v.y + v.z * v.z + v.w * v.w;
#pragma unroll
    for (int off = 16; off > 0; off >>= 1)
        ss += __shfl_xor_sync(0xffffffffu, ss, off);

    float inv = rsqrtf(ss * (1.0f / 128.0f) + 1e-6f) * scale;
    float4 wv = *(const float4*)&w[lane << 2];
    v.x *= inv * wv.x; v.y *= inv * wv.y;
    v.z *= inv * wv.z; v.w *= inv * wv.w;

    union { __nv_bfloat16 b[4]; uint2 u; } H, L;
    H.b[0] = __float2bfloat16(v.x);
    H.b[1] = __float2bfloat16(v.y);
    H.b[2] = __float2bfloat16(v.z);
    H.b[3] = __float2bfloat16(v.w);
    L.b[0] = __float2bfloat16(v.x - __bfloat162float(H.b[0]));
    L.b[1] = __float2bfloat16(v.y - __bfloat162float(H.b[1]));
    L.b[2] = __float2bfloat16(v.z - __bfloat162float(H.b[2]));
    L.b[3] = __float2bfloat16(v.w - __bfloat162float(H.b[3]));
    size_t o = (size_t)warp * 32 + lane;
    ((uint2*)hi)[o] = H.u;
    ((uint2*)lo)[o] = L.u;
}

// ---------------------------------------------------------------------------
// transpose + split V: in [4096][2048] fp32 -> VT hi/lo [2048][4096] bf16
// ---------------------------------------------------------------------------
__global__ void __launch_bounds__(256) transpose_split(
    const float* __restrict__ in, __nv_bfloat16* __restrict__ thi,
    __nv_bfloat16* __restrict__ tlo) {
    __shared__ float t[32][33];
    const int s0 = blockIdx.x << 5;
    const int c0 = blockIdx.y << 5;
    const int tx = threadIdx.x & 31;
    const int ty = threadIdx.x >> 5;
#pragma unroll
    for (int i = 0; i < 4; i++) {
        int r = (ty << 2) + i;
        t[r][tx] = in[(size_t)(s0 + r) * 2048 + c0 + tx];
    }
    __syncthreads();
#pragma unroll
    for (int i = 0; i < 4; i++) {
        int r = (ty << 2) + i;
        float v = t[tx][r];
        __nv_bfloat16 h = __float2bfloat16(v);
        __nv_bfloat16 l = __float2bfloat16(v - __bfloat162float(h));
        size_t o = (size_t)(c0 + r) * 4096 + s0 + tx;
        thi[o] = h;
        tlo[o] = l;
    }
}

// ---------------------------------------------------------------------------
// gemm_mma v3b: fused 3-pass per K-chunk, PASS-OUTER MMA ordering (RAW-chain
// separation 4 instead of 1). Arithmetic order per accumulator unchanged.
// C[4096,2048] = (Ahi+Alo)[4096,2048] * (Bhi+Blo)[2048,2048]^T
// CTA 128x128, 8 warps (warp 64x32), K chunk 32, 3-stage cp.async, 1 sync/iter.
// ---------------------------------------------------------------------------
#define GMS      32768              // stage: 4 tiles x 8KB
#define GM_SMEM  (3 * GMS)          // 98304

__global__ void __launch_bounds__(256, 2) gemm_mma(
    const __nv_bfloat16* __restrict__ Ahi, const __nv_bfloat16* __restrict__ Alo,
    const __nv_bfloat16* __restrict__ Bhi, const __nv_bfloat16* __restrict__ Blo,
    float* __restrict__ C) {
    constexpr int Nd = 2048, Kd = 2048;
    extern __shared__ char smem[];
    const uint32_t sbase = smem_u32(smem);
    const int tid = threadIdx.x;
    const int lane = tid & 31;
    const int wid = tid >> 5;
    const int m0 = blockIdx.y << 7;
    const int n0 = blockIdx.x << 7;
    const int wm = (wid & 1) << 6;       // 0/64
    const int wn = (wid >> 1) << 5;      // 0/32/64/96

    float acc[4][4][4];
#pragma unroll
    for (int mi = 0; mi < 4; mi++)
#pragma unroll
        for (int ni = 0; ni < 4; ni++)
#pragma unroll
            for (int q = 0; q < 4; q++) acc[mi][ni][q] = 0.f;

    const int lr = tid >> 1;             // row 0..127
    const int lc0 = (tid & 1) << 1;      // chunk 0 or 2

    auto issue = [&](int it, int stage) {
        int kk = it << 5;                // k elements
        const __nv_bfloat16* Ah = Ahi + (size_t)(m0 + lr) * Kd + kk;
        const __nv_bfloat16* Al = Alo + (size_t)(m0 + lr) * Kd + kk;
        const __nv_bfloat16* Bh = Bhi + (size_t)(n0 + lr) * Kd + kk;
        const __nv_bfloat16* Bl = Blo + (size_t)(n0 + lr) * Kd + kk;
        uint32_t st = sbase + stage * GMS + lr * 64;
#pragma unroll
        for (int j = 0; j < 2; j++) {
            int c = lc0 + j;
            uint32_t sw = (uint32_t)((c ^ ((lr >> 1) & 3)) << 4);
            CP_ASYNC16(st + sw,         Ah + c * 8);
            CP_ASYNC16(st + 8192 + sw,  Al + c * 8);
            CP_ASYNC16(st + 16384 + sw, Bh + c * 8);
            CP_ASYNC16(st + 24576 + sw, Bl + c * 8);
        }
    };

    issue(0, 0); CP_COMMIT();
    issue(1, 1); CP_COMMIT();

    constexpr int NITER = 64;            // 2048 / 32
    int stage = 0, nstage = 2;
    for (int it = 0; it < NITER; it++) {
        if (it < NITER - 1) CP_WAIT1(); else CP_WAIT0();
        __syncthreads();
        if (it + 2 < NITER) { issue(it + 2, nstage); CP_COMMIT(); }

        const uint32_t sAh = sbase + stage * GMS;
        const uint32_t sAl = sAh + 8192;
        const uint32_t sBh = sAh + 16384;
        const uint32_t sBl = sAh + 24576;

#pragma unroll
        for (int ks = 0; ks < 2; ks++) {
            uint32_t bh[2][4], bl[2][4];
#pragma unroll
            for (int pr = 0; pr < 2; pr++) {
                int row = wn + pr * 16 + (lane & 7) + (((lane >> 4) & 1) << 3);
                int c = ks * 2 + ((lane >> 3) & 1);
                uint32_t off = (uint32_t)(row * 64 + ((c ^ ((row >> 1) & 3)) << 4));
                LDSM_X4(bh[pr], sBh + off);
                LDSM_X4(bl[pr], sBl + off);
            }
#pragma unroll
            for (int mi = 0; mi < 4; mi++) {
                uint32_t ah[4], al[4];
                int row = wm + mi * 16 + (lane & 15);
                int c = ks * 2 + (lane >> 4);
                uint32_t off = (uint32_t)(row * 64 + ((c ^ ((row >> 1) & 3)) << 4));
                LDSM_X4(ah, sAh + off);
                LDSM_X4(al, sAl + off);
                // pass-outer: same-acc reuse distance 4 (was 1)
#pragma unroll
                for (int ni = 0; ni < 4; ni++)
                    MMA16816(acc[mi][ni], ah,
                             bh[ni >> 1][(ni & 1) << 1],
                             bh[ni >> 1][((ni & 1) << 1) + 1]);
#pragma unroll
                for (int ni = 0; ni < 4; ni++)
                    MMA16816(acc[mi][ni], ah,
                             bl[ni >> 1][(ni & 1) << 1],
                             bl[ni >> 1][((ni & 1) << 1) + 1]);
#pragma unroll
                for (int ni = 0; ni < 4; ni++)
                    MMA16816(acc[mi][ni], al,
                             bh[ni >> 1][(ni & 1) << 1],
                             bh[ni >> 1][((ni & 1) << 1) + 1]);
            }
        }
        stage = (stage == 2) ? 0 : stage + 1;
        nstage = (nstage == 2) ? 0 : nstage + 1;
    }

    // epilogue
#pragma unroll
    for (int mi = 0; mi < 4; mi++) {
        int r0 = m0 + wm + mi * 16 + (lane >> 2);
#pragma unroll
        for (int ni = 0; ni < 4; ni++) {
            int cc = n0 + wn + ni * 8 + ((lane & 3) << 1);
            *(float2*)&C[(size_t)r0 * Nd + cc] =
                make_float2(acc[mi][ni][0], acc[mi][ni][1]);
            *(float2*)&C[(size_t)(r0 + 8) * Nd + cc] =
                make_float2(acc[mi][ni][2], acc[mi][ni][3]);
        }
    }
}

// ---------------------------------------------------------------------------
// Flash attention, mma.sync bf16 hi/lo (3-pass), pass-outer MMA ordering.
// 128 queries x one head per CTA, 8 warps. K tiles of 64, 2-stage cp.async.
// Epilogue writes bf16 hi/lo directly (feeds the O-projection GEMM).
// ---------------------------------------------------------------------------
#define FM_QHI   0
#define FM_QLO   32768
#define FM_STG0  65536
#define FM_STAGE 65536               // Khi | Klo | Vhi | Vlo @ 16KB each
#define FM_SMEM  (65536 + 2 * FM_STAGE)   // 196608

__device__ __forceinline__ uint32_t sw256(int row, int kb) {
    return (uint32_t)(row * 256 + ((kb & 0x80) | ((kb ^ ((row & 7) << 4)) & 0x70)));
}

__global__ void __launch_bounds__(256, 1) flash_mma(
    const __nv_bfloat16* __restrict__ Qhi, const __nv_bfloat16* __restrict__ Qlo,
    const __nv_bfloat16* __restrict__ Khi, const __nv_bfloat16* __restrict__ Klo,
    const __nv_bfloat16* __restrict__ VThi, const __nv_bfloat16* __restrict__ VTlo,
    __nv_bfloat16* __restrict__ Ohi, __nv_bfloat16* __restrict__ Olo) {
    extern __shared__ char smem[];
    const uint32_t sb = smem_u32(smem);
    const int tid = threadIdx.x;
    const int lane = tid & 31;
    const int wid = tid >> 5;
    const int h = blockIdx.y;
    const int m0 = blockIdx.x << 7;
    const int hoff = h << 7;
    const int qbase = wid << 4;

    // ---- load Q tiles (hi/lo) ----
    {
        int row = tid >> 1;
        int c0 = (tid & 1) << 3;
        const __nv_bfloat16* qh = Qhi + (size_t)(m0 + row) * 2048 + hoff;
        const __nv_bfloat16* ql = Qlo + (size_t)(m0 + row) * 2048 + hoff;
#pragma unroll
        for (int j = 0; j < 8; j++) {
            int c = c0 + j;
            uint32_t sw = sw256(row, c << 4);
            CP_ASYNC16(sb + FM_QHI + sw, qh + c * 8);
            CP_ASYNC16(sb + FM_QLO + sw, ql + c * 8);
        }
    }

    const int krow = tid >> 2;
    const int kc0 = (tid & 3) << 2;
    const int vrow = tid >> 1;
    const int vc0 = (tid & 1) << 2;

#define FM_ISSUE(kt, buf) do {                                                  \
    uint32_t _st = sb + FM_STG0 + (buf) * FM_STAGE;                             \
    const __nv_bfloat16* _kh = Khi + (size_t)((kt) + krow) * 2048 + hoff;       \
    const __nv_bfloat16* _kl = Klo + (size_t)((kt) + krow) * 2048 + hoff;       \
    _Pragma("unroll")                                                           \
    for (int _j = 0; _j < 4; _j++) {                                            \
        int _c = kc0 + _j;                                                      \
        uint32_t _sw = sw256(krow, _c << 4);                                    \
        CP_ASYNC16(_st + _sw, _kh + _c * 8);                                    \
        CP_ASYNC16(_st + 16384 + _sw, _kl + _c * 8);                            \
    }                                                                           \
    const __nv_bfloat16* _vh = VThi + (size_t)(hoff + vrow) * 4096 + (kt);      \
    const __nv_bfloat16* _vl = VTlo + (size_t)(hoff + vrow) * 4096 + (kt);      \
    _Pragma("unroll")                                                           \
    for (int _j = 0; _j < 4; _j++) {                                            \
        int _c = vc0 + _j;                                                      \
        uint32_t _sw = (uint32_t)(vrow * 128 + ((_c << 4) ^ ((vrow & 7) << 4)));\
        CP_ASYNC16(_st + 32768 + _sw, _vh + _c * 8);                            \
        CP_ASYNC16(_st + 49152 + _sw, _vl + _c * 8);                            \
    }                                                                           \
} while (0)

    FM_ISSUE(0, 0);
    CP_COMMIT();

    float m0s = -1e30f, m1s = -1e30f, l0 = 0.f, l1 = 0.f;
    float o[16][4];
#pragma unroll
    for (int j = 0; j < 16; j++)
#pragma unroll
        for (int q = 0; q < 4; q++) o[j][q] = 0.f;

    const int NITER = 4096 / 64;
    for (int it = 0; it < NITER; it++) {
        const int buf = it & 1;
        CP_WAIT0();
        __syncthreads();
        if (it + 1 < NITER) {
            FM_ISSUE((it + 1) << 6, buf ^ 1);
            CP_COMMIT();
        }

        const uint32_t sKh = sb + FM_STG0 + buf * FM_STAGE;
        const uint32_t sKl = sKh + 16384;
        const uint32_t sVh = sKh + 32768;
        const uint32_t sVl = sKh + 49152;

        // ---- S = Q K^T (3-pass, pass-outer: reuse distance 8) ----
        float s[8][4];
#pragma unroll
        for (int j = 0; j < 8; j++)
#pragma unroll
            for (int q = 0; q < 4; q++) s[j][q] = 0.f;

#pragma unroll
        for (int ks = 0; ks < 8; ks++) {
            uint32_t ah[4], al[4], bh[4][4], bl[4][4];
            {
                int row = qbase + (lane & 15);
                int kb = ks * 32 + ((lane >> 4) << 4);
                LDSM_X4(ah, sb + FM_QHI + sw256(row, kb));
                LDSM_X4(al, sb + FM_QLO + sw256(row, kb));
            }
#pragma unroll
            for (int pr = 0; pr < 4; pr++) {
                int row = pr * 16 + (lane & 7) + (((lane >> 4) & 1) << 3);
                int kb = ks * 32 + (((lane >> 3) & 1) << 4);
                uint32_t sw = sw256(row, kb);
                LDSM_X4(bh[pr], sKh + sw);
                LDSM_X4(bl[pr], sKl + sw);
            }
#pragma unroll
            for (int j = 0; j < 8; j++)
                MMA16816(s[j], ah, bh[j >> 1][(j & 1) << 1],
                         bh[j >> 1][((j & 1) << 1) + 1]);
#pragma unroll
            for (int j = 0; j < 8; j++)
                MMA16816(s[j], ah, bl[j >> 1][(j & 1) << 1],
                         bl[j >> 1][((j & 1) << 1) + 1]);
#pragma unroll
            for (int j = 0; j < 8; j++)
                MMA16816(s[j], al, bh[j >> 1][(j & 1) << 1],
                         bh[j >> 1][((j & 1) << 1) + 1]);
        }

        // ---- online softmax (base-2) ----
        float mx0 = -1e30f, mx1 = -1e30f;
#pragma unroll
        for (int j = 0; j < 8; j++) {
            mx0 = fmaxf(mx0, fmaxf(s[j][0], s[j][1]));
            mx1 = fmaxf(mx1, fmaxf(s[j][2], s[j][3]));
        }
        mx0 = fmaxf(mx0, __shfl_xor_sync(0xffffffffu, mx0, 1));
        mx0 = fmaxf(mx0, __shfl_xor_sync(0xffffffffu, mx0, 2));
        mx1 = fmaxf(mx1, __shfl_xor_sync(0xffffffffu, mx1, 1));
        mx1 = fmaxf(mx1, __shfl_xor_sync(0xffffffffu, mx1, 2));
        float mn0 = fmaxf(m0s, mx0), mn1 = fmaxf(m1s, mx1);
        float corr0 = ex2(m0s - mn0), corr1 = ex2(m1s - mn1);
        m0s = mn0; m1s = mn1;

        float sum0 = 0.f, sum1 = 0.f;
        float p[8][4];
#pragma unroll
        for (int j = 0; j < 8; j++) {
            p[j][0] = ex2(s[j][0] - mn0);
            p[j][1] = ex2(s[j][1] - mn0);
            p[j][2] = ex2(s[j][2] - mn1);
            p[j][3] = ex2(s[j][3] - mn1);
            sum0 += p[j][0] + p[j][1];
            sum1 += p[j][2] + p[j][3];
        }
        sum0 += __shfl_xor_sync(0xffffffffu, sum0, 1);
        sum0 += __shfl_xor_sync(0xffffffffu, sum0, 2);
        sum1 += __shfl_xor_sync(0xffffffffu, sum1, 1);
        sum1 += __shfl_xor_sync(0xffffffffu, sum1, 2);
        l0 = l0 * corr0 + sum0;
        l1 = l1 * corr1 + sum1;

        // pack P -> bf16 hi/lo A-fragments
        uint32_t pahi[4][4], palo[4][4];
#pragma unroll
        for (int kt = 0; kt < 4; kt++) {
#pragma unroll
            for (int t = 0; t < 2; t++) {
                int j = 2 * kt + t;
#pragma unroll
                for (int half = 0; half < 2; half++) {
                    float f0 = p[j][half * 2], f1 = p[j][half * 2 + 1];
                    __nv_bfloat162 hh = __floats2bfloat162_rn(f0, f1);
                    float r0 = f0 - __low2float(hh);
                    float r1 = f1 - __high2float(hh);
                    __nv_bfloat162 ll = __floats2bfloat162_rn(r0, r1);
                    pahi[kt][t * 2 + half] = *(uint32_t*)&hh;
                    palo[kt][t * 2 + half] = *(uint32_t*)&ll;
                }
            }
        }

#pragma unroll
        for (int j = 0; j < 16; j++) {
            o[j][0] *= corr0; o[j][1] *= corr0;
            o[j][2] *= corr1; o[j][3] *= corr1;
        }

        // ---- O += P V (3-pass, pr pairs, pass-outer: reuse distance 4) ----
#pragma unroll
        for (int kt = 0; kt < 4; kt++) {
#pragma unroll
            for (int prp = 0; prp < 4; prp++) {
                uint32_t bvh[2][4], bvl[2][4];
#pragma unroll
                for (int e = 0; e < 2; e++) {
                    int pr = prp * 2 + e;
                    int row = pr * 16 + (lane & 7) + (((lane >> 4) & 1) << 3);
                    int kb = kt * 32 + (((lane >> 3) & 1) << 4);
                    uint32_t sw = (uint32_t)(row * 128 + (kb ^ ((row & 7) << 4)));
                    LDSM_X4(bvh[e], sVh + sw);
                    LDSM_X4(bvl[e], sVl + sw);
                }
                // accs j = 4*prp + q, q = e*2 + t  (e = which pr, t = n-half)
#pragma unroll
                for (int q = 0; q < 4; q++)
                    MMA16816(o[prp * 4 + q], pahi[kt],
                             bvh[q >> 1][(q & 1) << 1],
                             bvh[q >> 1][((q & 1) << 1) + 1]);
#pragma unroll
                for (int q = 0; q < 4; q++)
                    MMA16816(o[prp * 4 + q], pahi[kt],
                             bvl[q >> 1][(q & 1) << 1],
                             bvl[q >> 1][((q & 1) << 1) + 1]);
#pragma unroll
                for (int q = 0; q < 4; q++)
                    MMA16816(o[prp * 4 + q], palo[kt],
                             bvh[q >> 1][(q & 1) << 1],
                             bvh[q >> 1][((q & 1) << 1) + 1]);
            }
        }
    }

    // ---- epilogue: write bf16 hi/lo directly ----
    // acc index j = prp*4 + e*2 + t where pr = prp*2+e; output ntile = pr*2+t
    float inv0 = 1.0f / l0, inv1 = 1.0f / l1;
    int r0 = m0 + qbase + (lane >> 2);
#pragma unroll
    for (int j = 0; j < 16; j++) {
        int prp = j >> 2, e = (j >> 1) & 1, t = j & 1;
        int ntile = (prp * 2 + e) * 2 + t;
        int cc = hoff + ntile * 8 + ((lane & 3) << 1);
        {
            float v0 = o[j][0] * inv0, v1 = o[j][1] * inv0;
            __nv_bfloat162 hh = __floats2bfloat162_rn(v0, v1);
            __nv_bfloat162 ll = __floats2bfloat162_rn(v0 - __low2float(hh),
                                                      v1 - __high2float(hh));
            *(uint32_t*)&Ohi[(size_t)r0 * 2048 + cc] = *(uint32_t*)&hh;
            *(uint32_t*)&Olo[(size_t)r0 * 2048 + cc] = *(uint32_t*)&ll;
        }
        {
            float v0 = o[j][2] * inv1, v1 = o[j][3] * inv1;
            __nv_bfloat162 hh = __floats2bfloat162_rn(v0, v1);
            __nv_bfloat162 ll = __floats2bfloat162_rn(v0 - __low2float(hh),
                                                      v1 - __high2float(hh));
            *(uint32_t*)&Ohi[(size_t)(r0 + 8) * 2048 + cc] = *(uint32_t*)&hh;
            *(uint32_t*)&Olo[(size_t)(r0 + 8) * 2048 + cc] = *(uint32_t*)&ll;
        }
    }
}

// ---------------------------------------------------------------------------
// Launch
// ---------------------------------------------------------------------------
extern "C" void kernel_launch(void* const* d_in, const int* in_sizes, int n_in,
                              void* d_out, int out_size) {
    const float* x  = (const float*)d_in[0];
    const float* wq = (const float*)d_in[1];
    const float* wk = (const float*)d_in[2];
    const float* wv = (const float*)d_in[3];
    const float* wo = (const float*)d_in[4];
    const float* qn = (const float*)d_in[5];
    const float* kn = (const float*)d_in[6];
    float* out = (float*)d_out;

    void *pq, *pk, *pv, *pxh, *pxl, *pwh, *pwl;
    void *pqh, *pql, *pkh, *pkl, *pvh, *pvl;
    cudaGetSymbolAddress(&pq, g_Q);
    cudaGetSymbolAddress(&pk, g_K);
    cudaGetSymbolAddress(&pv, g_V);
    cudaGetSymbolAddress(&pxh, g_Xhi);
    cudaGetSymbolAddress(&pxl, g_Xlo);
    cudaGetSymbolAddress(&pwh, g_Whi);
    cudaGetSymbolAddress(&pwl, g_Wlo);
    cudaGetSymbolAddress(&pqh, g_Qhi);
    cudaGetSymbolAddress(&pql, g_Qlo);
    cudaGetSymbolAddress(&pkh, g_Khi);
    cudaGetSymbolAddress(&pkl, g_Klo);
    cudaGetSymbolAddress(&pvh, g_VThi);
    cudaGetSymbolAddress(&pvl, g_VTlo);
    float* Q = (float*)pq;
    float* K = (float*)pk;
    float* V = (float*)pv;
    __nv_bfloat16* Xhi = (__nv_bfloat16*)pxh;
    __nv_bfloat16* Xlo = (__nv_bfloat16*)pxl;
    __nv_bfloat16* Whi = (__nv_bfloat16*)pwh;
    __nv_bfloat16* Wlo = (__nv_bfloat16*)pwl;

    cudaFuncSetAttribute(gemm_mma, cudaFuncAttributeMaxDynamicSharedMemorySize, GM_SMEM);
    cudaFuncSetAttribute(flash_mma, cudaFuncAttributeMaxDynamicSharedMemorySize, FM_SMEM);

    const int M = 4096, D = 2048;
    const int nX4 = M * D / 4;
    const int nW4 = D * D / 4;
    dim3 gg(D / 128, M / 128);      // (16, 32)

    split_bf16<<<(nX4 + 255) / 256, 256>>>(x, Xhi, Xlo, nX4, 1.0f);

    split_bf16<<<(nW4 + 255) / 256, 256>>>(wq, Whi, Wlo, nW4, 1.0f);
    gemm_mma<<<gg, 256, GM_SMEM>>>(Xhi, Xlo, Whi, Wlo, Q);

    split_bf16<<<(nW4 + 255) / 256, 256>>>(wk, Whi, Wlo, nW4, 1.0f);
    gemm_mma<<<gg, 256, GM_SMEM>>>(Xhi, Xlo, Whi, Wlo, K);

    split_bf16<<<(nW4 + 255) / 256, 256>>>(wv, Whi, Wlo, nW4, 1.0f);
    gemm_mma<<<gg, 256, GM_SMEM>>>(Xhi, Xlo, Whi, Wlo, V);

    // fused rmsnorm + scale + bf16 split (qscale = 1/sqrt(128) * log2(e))
    const float qscale = 0.08838834764831845f * 1.4426950408889634f;
    int nrows = M * 16;
    rmsnorm_split<<<nrows / 8, 256>>>(Q, qn, (__nv_bfloat16*)pqh,
                                      (__nv_bfloat16*)pql, nrows, qscale);
    rmsnorm_split<<<nrows / 8, 256>>>(K, kn, (__nv_bfloat16*)pkh,
                                      (__nv_bfloat16*)pkl, nrows, 1.0f);
    transpose_split<<<dim3(M / 32, D / 32), 256>>>(V, (__nv_bfloat16*)pvh,
                                                   (__nv_bfloat16*)pvl);

    // flash writes bf16 hi/lo directly into Xhi/Xlo (A operand of O-proj)
    flash_mma<<<dim3(M / 128, 16), 256, FM_SMEM>>>(
        (__nv_bfloat16*)pqh, (__nv_bfloat16*)pql,
        (__nv_bfloat16*)pkh, (__nv_bfloat16*)pkl,
        (__nv_bfloat16*)pvh, (__nv_bfloat16*)pvl, Xhi, Xlo);

    split_bf16<<<(nW4 + 255) / 256, 256>>>(wo, Whi, Wlo, nW4, 1.0f);
    gemm_mma<<<gg, 256, GM_SMEM>>>(Xhi, Xlo, Whi, Wlo, out);
}

// round 10
// speedup vs baseline: 2.7645x; 1.4704x over previous
#include <cuda_runtime.h>
#include <cuda_fp16.h>
#include <cstdint>
#include <math.h>

// ---------------- scratch (static device globals; no allocation) ----------
__device__ float g_Q[4096 * 2048];
__device__ float g_K[4096 * 2048];
__device__ float g_V[4096 * 2048];
__device__ __half g_Xh[4096 * 2048];     // activation fp16 hi limb (GEMM A)
__device__ __half g_Xl[4096 * 2048];     // activation fp16 lo limb
__device__ __half g_Wh[2048 * 2048];     // weight fp16 (single)
__device__ __half g_Qh[4096 * 2048];
__device__ __half g_Ql[4096 * 2048];
__device__ __half g_Kh[4096 * 2048];
__device__ __half g_VTh[2048 * 4096];    // [h*128+d][s], fp16
 
// ======================= portable PTX helpers (sm_80+) =====================
__device__ __forceinline__ uint32_t smem_u32(const void* p) {
    uint32_t a;
    asm("{ .reg .u64 t; cvta.to.shared.u64 t, %1; cvt.u32.u64 %0, t; }"
        : "=r"(a) : "l"(p));
    return a;
}
#define CP_ASYNC16(dst, src) \
    asm volatile("cp.async.cg.shared.global [%0], [%1], 16;" \
                 :: "r"(dst), "l"(src))
#define CP_COMMIT() asm volatile("cp.async.commit_group;")
#define CP_WAIT1()  asm volatile("cp.async.wait_group 1;")
#define CP_WAIT0()  asm volatile("cp.async.wait_group 0;")
#define LDSM_X4(r, addr) \
    asm volatile("ldmatrix.sync.aligned.m8n8.x4.shared.b16 {%0,%1,%2,%3}, [%4];" \
                 : "=r"((r)[0]), "=r"((r)[1]), "=r"((r)[2]), "=r"((r)[3]) \
                 : "r"(addr))
#define MMAF16(d, a, b0, b1) \
    asm volatile("mma.sync.aligned.m16n8k16.row.col.f32.f16.f16.f32 " \
                 "{%0,%1,%2,%3}, {%4,%5,%6,%7}, {%8,%9}, {%0,%1,%2,%3};" \
                 : "+f"((d)[0]), "+f"((d)[1]), "+f"((d)[2]), "+f"((d)[3]) \
                 : "r"((a)[0]), "r"((a)[1]), "r"((a)[2]), "r"((a)[3]), \
                   "r"(b0), "r"(b1))
__device__ __forceinline__ float ex2(float x) {
    float r;
    asm("ex2.approx.f32 %0, %1;" : "=f"(r) : "f"(x));
    return r;
}

// ---------------------------------------------------------------------------
// split fp32 -> fp16 hi + fp16 lo (scale folded in)
// ---------------------------------------------------------------------------
__global__ void __launch_bounds__(256) split_h2(const float* __restrict__ in,
                                                __half* __restrict__ hi,
                                                __half* __restrict__ lo,
                                                int n4, float scale) {
    int i = blockIdx.x * blockDim.x + threadIdx.x;
    if (i >= n4) return;
    float4 v = ((const float4*)in)[i];
    v.x *= scale; v.y *= scale; v.z *= scale; v.w *= scale;
    union { __half b[4]; uint2 u; } H, L;
    H.b[0] = __float2half_rn(v.x);
    H.b[1] = __float2half_rn(v.y);
    H.b[2] = __float2half_rn(v.z);
    H.b[3] = __float2half_rn(v.w);
    L.b[0] = __float2half_rn(v.x - __half2float(H.b[0]));
    L.b[1] = __float2half_rn(v.y - __half2float(H.b[1]));
    L.b[2] = __float2half_rn(v.z - __half2float(H.b[2]));
    L.b[3] = __float2half_rn(v.w - __half2float(H.b[3]));
    ((uint2*)hi)[i] = H.u;
    ((uint2*)lo)[i] = L.u;
}

// ---------------------------------------------------------------------------
// convert fp32 -> fp16 (weights)
// ---------------------------------------------------------------------------
__global__ void __launch_bounds__(256) conv_h(const float* __restrict__ in,
                                              __half* __restrict__ out, int n4) {
    int i = blockIdx.x * blockDim.x + threadIdx.x;
    if (i >= n4) return;
    float4 v = ((const float4*)in)[i];
    union { __half b[4]; uint2 u; } H;
    H.b[0] = __float2half_rn(v.x);
    H.b[1] = __float2half_rn(v.y);
    H.b[2] = __float2half_rn(v.z);
    H.b[3] = __float2half_rn(v.w);
    ((uint2*)out)[i] = H.u;
}

// ---------------------------------------------------------------------------
// fused rmsnorm + scale + fp16 hi/lo split (Q path)
// ---------------------------------------------------------------------------
__global__ void __launch_bounds__(256) rmsnorm_split_h2(
    const float* __restrict__ X, const float* __restrict__ w,
    __half* __restrict__ hi, __half* __restrict__ lo,
    int nrows, float scale) {
    int warp = (blockIdx.x * blockDim.x + threadIdx.x) >> 5;
    int lane = threadIdx.x & 31;
    if (warp >= nrows) return;

    float4 v = *(const float4*)&X[(size_t)warp * 128 + (lane << 2)];
    float ss = v.x * v.x + v.y * v.y + v.z * v.z + v.w * v.w;
#pragma unroll
    for (int off = 16; off > 0; off >>= 1)
        ss += __shfl_xor_sync(0xffffffffu, ss, off);

    float inv = rsqrtf(ss * (1.0f / 128.0f) + 1e-6f) * scale;
    float4 wv = *(const float4*)&w[lane << 2];
    v.x *= inv * wv.x; v.y *= inv * wv.y;
    v.z *= inv * wv.z; v.w *= inv * wv.w;

    union { __half b[4]; uint2 u; } H, L;
    H.b[0] = __float2half_rn(v.x);
    H.b[1] = __float2half_rn(v.y);
    H.b[2] = __float2half_rn(v.z);
    H.b[3] = __float2half_rn(v.w);
    L.b[0] = __float2half_rn(v.x - __half2float(H.b[0]));
    L.b[1] = __float2half_rn(v.y - __half2float(H.b[1]));
    L.b[2] = __float2half_rn(v.z - __half2float(H.b[2]));
    L.b[3] = __float2half_rn(v.w - __half2float(H.b[3]));
    size_t o = (size_t)warp * 32 + lane;
    ((uint2*)hi)[o] = H.u;
    ((uint2*)lo)[o] = L.u;
}

// ---------------------------------------------------------------------------
// fused rmsnorm + fp16 convert (K path, single precision output)
// ---------------------------------------------------------------------------
__global__ void __launch_bounds__(256) rmsnorm_h(
    const float* __restrict__ X, const float* __restrict__ w,
    __half* __restrict__ out, int nrows) {
    int warp = (blockIdx.x * blockDim.x + threadIdx.x) >> 5;
    int lane = threadIdx.x & 31;
    if (warp >= nrows) return;

    float4 v = *(const float4*)&X[(size_t)warp * 128 + (lane << 2)];
    float ss = v.x * v.x + v.y * v.y + v.z * v.z + v.w * v.w;
#pragma unroll
    for (int off = 16; off > 0; off >>= 1)
        ss += __shfl_xor_sync(0xffffffffu, ss, off);

    float inv = rsqrtf(ss * (1.0f / 128.0f) + 1e-6f);
    float4 wv = *(const float4*)&w[lane << 2];
    union { __half b[4]; uint2 u; } H;
    H.b[0] = __float2half_rn(v.x * inv * wv.x);
    H.b[1] = __float2half_rn(v.y * inv * wv.y);
    H.b[2] = __float2half_rn(v.z * inv * wv.z);
    H.b[3] = __float2half_rn(v.w * inv * wv.w);
    ((uint2*)out)[(size_t)warp * 32 + lane] = H.u;
}

// ---------------------------------------------------------------------------
// transpose + fp16 convert V: [4096][2048] fp32 -> VT [2048][4096] fp16
// ---------------------------------------------------------------------------
__global__ void __launch_bounds__(256) transpose_h(
    const float* __restrict__ in, __half* __restrict__ th) {
    __shared__ float t[32][33];
    const int s0 = blockIdx.x << 5;
    const int c0 = blockIdx.y << 5;
    const int tx = threadIdx.x & 31;
    const int ty = threadIdx.x >> 5;
#pragma unroll
    for (int i = 0; i < 4; i++) {
        int r = (ty << 2) + i;
        t[r][tx] = in[(size_t)(s0 + r) * 2048 + c0 + tx];
    }
    __syncthreads();
#pragma unroll
    for (int i = 0; i < 4; i++) {
        int r = (ty << 2) + i;
        th[(size_t)(c0 + r) * 4096 + s0 + tx] = __float2half_rn(t[tx][r]);
    }
}

// ---------------------------------------------------------------------------
// gemm fp16 2-pass:  C = (Ah + Al) * Bh^T   ==  exact-A x fp16(B)
// CTA 128x128, 8 warps (warp 64x32), K chunk 32 (64B rows), 3-stage cp.async,
// 1 sync/iter, NITER=64. Stage holds Ah|Al|Bh (24KB).
// ---------------------------------------------------------------------------
#define GMS      24576              // stage: 3 tiles x 8KB
#define GM_SMEM  (3 * GMS)          // 73728

__global__ void __launch_bounds__(256, 2) gemm_mma(
    const __half* __restrict__ Ah, const __half* __restrict__ Al,
    const __half* __restrict__ Bh, float* __restrict__ C) {
    constexpr int Nd = 2048, Kd = 2048;
    extern __shared__ char smem[];
    const uint32_t sbase = smem_u32(smem);
    const int tid = threadIdx.x;
    const int lane = tid & 31;
    const int wid = tid >> 5;
    const int m0 = blockIdx.y << 7;
    const int n0 = blockIdx.x << 7;
    const int wm = (wid & 1) << 6;       // 0/64
    const int wn = (wid >> 1) << 5;      // 0/32/64/96

    float acc[4][4][4];
#pragma unroll
    for (int mi = 0; mi < 4; mi++)
#pragma unroll
        for (int ni = 0; ni < 4; ni++)
#pragma unroll
            for (int q = 0; q < 4; q++) acc[mi][ni][q] = 0.f;

    const int lr = tid >> 1;             // row 0..127
    const int lc0 = (tid & 1) << 1;      // chunk 0 or 2

    auto issue = [&](int it, int stage) {
        int kk = it << 5;
        const __half* pAh = Ah + (size_t)(m0 + lr) * Kd + kk;
        const __half* pAl = Al + (size_t)(m0 + lr) * Kd + kk;
        const __half* pBh = Bh + (size_t)(n0 + lr) * Kd + kk;
        uint32_t st = sbase + stage * GMS + lr * 64;
#pragma unroll
        for (int j = 0; j < 2; j++) {
            int c = lc0 + j;
            uint32_t sw = (uint32_t)((c ^ ((lr >> 1) & 3)) << 4);
            CP_ASYNC16(st + sw,         pAh + c * 8);
            CP_ASYNC16(st + 8192 + sw,  pAl + c * 8);
            CP_ASYNC16(st + 16384 + sw, pBh + c * 8);
        }
    };

    issue(0, 0); CP_COMMIT();
    issue(1, 1); CP_COMMIT();

    constexpr int NITER = 64;            // 2048 / 32
    int stage = 0, nstage = 2;
    for (int it = 0; it < NITER; it++) {
        if (it < NITER - 1) CP_WAIT1(); else CP_WAIT0();
        __syncthreads();
        if (it + 2 < NITER) { issue(it + 2, nstage); CP_COMMIT(); }

        const uint32_t sAh = sbase + stage * GMS;
        const uint32_t sAl = sAh + 8192;
        const uint32_t sBh = sAh + 16384;

#pragma unroll
        for (int ks = 0; ks < 2; ks++) {
            uint32_t bh[2][4];
#pragma unroll
            for (int pr = 0; pr < 2; pr++) {
                int row = wn + pr * 16 + (lane & 7) + (((lane >> 4) & 1) << 3);
                int c = ks * 2 + ((lane >> 3) & 1);
                uint32_t off = (uint32_t)(row * 64 + ((c ^ ((row >> 1) & 3)) << 4));
                LDSM_X4(bh[pr], sBh + off);
            }
#pragma unroll
            for (int mi = 0; mi < 4; mi++) {
                uint32_t ah[4], al[4];
                int row = wm + mi * 16 + (lane & 15);
                int c = ks * 2 + (lane >> 4);
                uint32_t off = (uint32_t)(row * 64 + ((c ^ ((row >> 1) & 3)) << 4));
                LDSM_X4(ah, sAh + off);
                LDSM_X4(al, sAl + off);
#pragma unroll
                for (int ni = 0; ni < 4; ni++)
                    MMAF16(acc[mi][ni], ah,
                           bh[ni >> 1][(ni & 1) << 1],
                           bh[ni >> 1][((ni & 1) << 1) + 1]);
#pragma unroll
                for (int ni = 0; ni < 4; ni++)
                    MMAF16(acc[mi][ni], al,
                           bh[ni >> 1][(ni & 1) << 1],
                           bh[ni >> 1][((ni & 1) << 1) + 1]);
            }
        }
        stage = (stage == 2) ? 0 : stage + 1;
        nstage = (nstage == 2) ? 0 : nstage + 1;
    }

    // epilogue
#pragma unroll
    for (int mi = 0; mi < 4; mi++) {
        int r0 = m0 + wm + mi * 16 + (lane >> 2);
#pragma unroll
        for (int ni = 0; ni < 4; ni++) {
            int cc = n0 + wn + ni * 8 + ((lane & 3) << 1);
            *(float2*)&C[(size_t)r0 * Nd + cc] =
                make_float2(acc[mi][ni][0], acc[mi][ni][1]);
            *(float2*)&C[(size_t)(r0 + 8) * Nd + cc] =
                make_float2(acc[mi][ni][2], acc[mi][ni][3]);
        }
    }
}

// ---------------------------------------------------------------------------
// Flash attention fp16 2-pass: S = (Qh+Ql)*Kh^T ; O = (Ph+Pl)*Vh.
// 128 queries x one head per CTA, 8 warps. K tiles of 64, 2-stage cp.async.
// Epilogue writes fp16 hi/lo directly (A operand of O-projection).
// ---------------------------------------------------------------------------
#define FM_QH    0
#define FM_QL    32768
#define FM_STG0  65536
#define FM_STAGE 32768               // Kh 16KB | Vh 16KB
#define FM_SMEM  (65536 + 2 * FM_STAGE)   // 131072

__device__ __forceinline__ uint32_t sw256(int row, int kb) {
    return (uint32_t)(row * 256 + ((kb & 0x80) | ((kb ^ ((row & 7) << 4)) & 0x70)));
}

__global__ void __launch_bounds__(256, 1) flash_mma(
    const __half* __restrict__ Qh, const __half* __restrict__ Ql,
    const __half* __restrict__ Kh, const __half* __restrict__ VTh,
    __half* __restrict__ Oh, __half* __restrict__ Ol) {
    extern __shared__ char smem[];
    const uint32_t sb = smem_u32(smem);
    const int tid = threadIdx.x;
    const int lane = tid & 31;
    const int wid = tid >> 5;
    const int h = blockIdx.y;
    const int m0 = blockIdx.x << 7;
    const int hoff = h << 7;
    const int qbase = wid << 4;

    // ---- load Q tiles (hi/lo) ----
    {
        int row = tid >> 1;
        int c0 = (tid & 1) << 3;
        const __half* qh = Qh + (size_t)(m0 + row) * 2048 + hoff;
        const __half* ql = Ql + (size_t)(m0 + row) * 2048 + hoff;
#pragma unroll
        for (int j = 0; j < 8; j++) {
            int c = c0 + j;
            uint32_t sw = sw256(row, c << 4);
            CP_ASYNC16(sb + FM_QH + sw, qh + c * 8);
            CP_ASYNC16(sb + FM_QL + sw, ql + c * 8);
        }
    }

    const int krow = tid >> 2;           // 0..63
    const int kc0 = (tid & 3) << 2;
    const int vrow = tid >> 1;           // 0..127
    const int vc0 = (tid & 1) << 2;

#define FM_ISSUE(kt, buf) do {                                                  \
    uint32_t _st = sb + FM_STG0 + (buf) * FM_STAGE;                             \
    const __half* _kh = Kh + (size_t)((kt) + krow) * 2048 + hoff;               \
    _Pragma("unroll")                                                           \
    for (int _j = 0; _j < 4; _j++) {                                            \
        int _c = kc0 + _j;                                                      \
        CP_ASYNC16(_st + sw256(krow, _c << 4), _kh + _c * 8);                   \
    }                                                                           \
    const __half* _vh = VTh + (size_t)(hoff + vrow) * 4096 + (kt);              \
    _Pragma("unroll")                                                           \
    for (int _j = 0; _j < 4; _j++) {                                            \
        int _c = vc0 + _j;                                                      \
        uint32_t _sw = (uint32_t)(vrow * 128 + ((_c << 4) ^ ((vrow & 7) << 4)));\
        CP_ASYNC16(_st + 16384 + _sw, _vh + _c * 8);                            \
    }                                                                           \
} while (0)

    FM_ISSUE(0, 0);
    CP_COMMIT();

    float m0s = -1e30f, m1s = -1e30f, l0 = 0.f, l1 = 0.f;
    float o[16][4];
#pragma unroll
    for (int j = 0; j < 16; j++)
#pragma unroll
        for (int q = 0; q < 4; q++) o[j][q] = 0.f;

    const int NITER = 4096 / 64;
    for (int it = 0; it < NITER; it++) {
        const int buf = it & 1;
        CP_WAIT0();
        __syncthreads();
        if (it + 1 < NITER) {
            FM_ISSUE((it + 1) << 6, buf ^ 1);
            CP_COMMIT();
        }

        const uint32_t sKh = sb + FM_STG0 + buf * FM_STAGE;
        const uint32_t sVh = sKh + 16384;

        // ---- S = Q K^T (2-pass) ----
        float s[8][4];
#pragma unroll
        for (int j = 0; j < 8; j++)
#pragma unroll
            for (int q = 0; q < 4; q++) s[j][q] = 0.f;

#pragma unroll
        for (int ks = 0; ks < 8; ks++) {
            uint32_t ah[4], al[4], bh[4][4];
            {
                int row = qbase + (lane & 15);
                int kb = ks * 32 + ((lane >> 4) << 4);
                LDSM_X4(ah, sb + FM_QH + sw256(row, kb));
                LDSM_X4(al, sb + FM_QL + sw256(row, kb));
            }
#pragma unroll
            for (int pr = 0; pr < 4; pr++) {
                int row = pr * 16 + (lane & 7) + (((lane >> 4) & 1) << 3);
                int kb = ks * 32 + (((lane >> 3) & 1) << 4);
                LDSM_X4(bh[pr], sKh + sw256(row, kb));
            }
#pragma unroll
            for (int j = 0; j < 8; j++)
                MMAF16(s[j], ah, bh[j >> 1][(j & 1) << 1],
                       bh[j >> 1][((j & 1) << 1) + 1]);
#pragma unroll
            for (int j = 0; j < 8; j++)
                MMAF16(s[j], al, bh[j >> 1][(j & 1) << 1],
                       bh[j >> 1][((j & 1) << 1) + 1]);
        }

        // ---- online softmax (base-2) ----
        float mx0 = -1e30f, mx1 = -1e30f;
#pragma unroll
        for (int j = 0; j < 8; j++) {
            mx0 = fmaxf(mx0, fmaxf(s[j][0], s[j][1]));
            mx1 = fmaxf(mx1, fmaxf(s[j][2], s[j][3]));
        }
        mx0 = fmaxf(mx0, __shfl_xor_sync(0xffffffffu, mx0, 1));
        mx0 = fmaxf(mx0, __shfl_xor_sync(0xffffffffu, mx0, 2));
        mx1 = fmaxf(mx1, __shfl_xor_sync(0xffffffffu, mx1, 1));
        mx1 = fmaxf(mx1, __shfl_xor_sync(0xffffffffu, mx1, 2));
        float mn0 = fmaxf(m0s, mx0), mn1 = fmaxf(m1s, mx1);
        float corr0 = ex2(m0s - mn0), corr1 = ex2(m1s - mn1);
        m0s = mn0; m1s = mn1;

        float sum0 = 0.f, sum1 = 0.f;
        float p[8][4];
#pragma unroll
        for (int j = 0; j < 8; j++) {
            p[j][0] = ex2(s[j][0] - mn0);
            p[j][1] = ex2(s[j][1] - mn0);
            p[j][2] = ex2(s[j][2] - mn1);
            p[j][3] = ex2(s[j][3] - mn1);
            sum0 += p[j][0] + p[j][1];
            sum1 += p[j][2] + p[j][3];
        }
        sum0 += __shfl_xor_sync(0xffffffffu, sum0, 1);
        sum0 += __shfl_xor_sync(0xffffffffu, sum0, 2);
        sum1 += __shfl_xor_sync(0xffffffffu, sum1, 1);
        sum1 += __shfl_xor_sync(0xffffffffu, sum1, 2);
        l0 = l0 * corr0 + sum0;
        l1 = l1 * corr1 + sum1;

        // pack P -> fp16 hi/lo A-fragments
        uint32_t pahi[4][4], palo[4][4];
#pragma unroll
        for (int kt = 0; kt < 4; kt++) {
#pragma unroll
            for (int t = 0; t < 2; t++) {
                int j = 2 * kt + t;
#pragma unroll
                for (int half = 0; half < 2; half++) {
                    float f0 = p[j][half * 2], f1 = p[j][half * 2 + 1];
                    __half2 hh = __floats2half2_rn(f0, f1);
                    float r0 = f0 - __half2float(__low2half(hh));
                    float r1 = f1 - __half2float(__high2half(hh));
                    __half2 ll = __floats2half2_rn(r0, r1);
                    pahi[kt][t * 2 + half] = *(uint32_t*)&hh;
                    palo[kt][t * 2 + half] = *(uint32_t*)&ll;
                }
            }
        }

#pragma unroll
        for (int j = 0; j < 16; j++) {
            o[j][0] *= corr0; o[j][1] *= corr0;
            o[j][2] *= corr1; o[j][3] *= corr1;
        }

        // ---- O += P V (2-pass) ----
#pragma unroll
        for (int kt = 0; kt < 4; kt++) {
#pragma unroll
            for (int prp = 0; prp < 4; prp++) {
                uint32_t bvh[2][4];
#pragma unroll
                for (int e = 0; e < 2; e++) {
                    int pr = prp * 2 + e;
                    int row = pr * 16 + (lane & 7) + (((lane >> 4) & 1) << 3);
                    int kb = kt * 32 + (((lane >> 3) & 1) << 4);
                    uint32_t sw = (uint32_t)(row * 128 + (kb ^ ((row & 7) << 4)));
                    LDSM_X4(bvh[e], sVh + sw);
                }
#pragma unroll
                for (int q = 0; q < 4; q++)
                    MMAF16(o[prp * 4 + q], pahi[kt],
                           bvh[q >> 1][(q & 1) << 1],
                           bvh[q >> 1][((q & 1) << 1) + 1]);
#pragma unroll
                for (int q = 0; q < 4; q++)
                    MMAF16(o[prp * 4 + q], palo[kt],
                           bvh[q >> 1][(q & 1) << 1],
                           bvh[q >> 1][((q & 1) << 1) + 1]);
            }
        }
    }

    // ---- epilogue: write fp16 hi/lo (O-proj A operand) ----
    // acc j = prp*4 + e*2 + t where pr = prp*2+e; output ntile = pr*2+t
    float inv0 = 1.0f / l0, inv1 = 1.0f / l1;
    int r0 = m0 + qbase + (lane >> 2);
#pragma unroll
    for (int j = 0; j < 16; j++) {
        int prp = j >> 2, e = (j >> 1) & 1, t = j & 1;
        int ntile = (prp * 2 + e) * 2 + t;
        int cc = hoff + ntile * 8 + ((lane & 3) << 1);
        {
            float v0 = o[j][0] * inv0, v1 = o[j][1] * inv0;
            __half2 hh = __floats2half2_rn(v0, v1);
            __half2 ll = __floats2half2_rn(v0 - __half2float(__low2half(hh)),
                                           v1 - __half2float(__high2half(hh)));
            *(uint32_t*)&Oh[(size_t)r0 * 2048 + cc] = *(uint32_t*)&hh;
            *(uint32_t*)&Ol[(size_t)r0 * 2048 + cc] = *(uint32_t*)&ll;
        }
        {
            float v0 = o[j][2] * inv1, v1 = o[j][3] * inv1;
            __half2 hh = __floats2half2_rn(v0, v1);
            __half2 ll = __floats2half2_rn(v0 - __half2float(__low2half(hh)),
                                           v1 - __half2float(__high2half(hh)));
            *(uint32_t*)&Oh[(size_t)(r0 + 8) * 2048 + cc] = *(uint32_t*)&hh;
            *(uint32_t*)&Ol[(size_t)(r0 + 8) * 2048 + cc] = *(uint32_t*)&ll;
        }
    }
}

// ---------------------------------------------------------------------------
// Launch
// ---------------------------------------------------------------------------
extern "C" void kernel_launch(void* const* d_in, const int* in_sizes, int n_in,
                              void* d_out, int out_size) {
    const float* x  = (const float*)d_in[0];
    const float* wq = (const float*)d_in[1];
    const float* wk = (const float*)d_in[2];
    const float* wv = (const float*)d_in[3];
    const float* wo = (const float*)d_in[4];
    const float* qn = (const float*)d_in[5];
    const float* kn = (const float*)d_in[6];
    float* out = (float*)d_out;

    void *pq, *pk, *pv, *pxh, *pxl, *pwh;
    void *pqh, *pql, *pkh, *pvt;
    cudaGetSymbolAddress(&pq, g_Q);
    cudaGetSymbolAddress(&pk, g_K);
    cudaGetSymbolAddress(&pv, g_V);
    cudaGetSymbolAddress(&pxh, g_Xh);
    cudaGetSymbolAddress(&pxl, g_Xl);
    cudaGetSymbolAddress(&pwh, g_Wh);
    cudaGetSymbolAddress(&pqh, g_Qh);
    cudaGetSymbolAddress(&pql, g_Ql);
    cudaGetSymbolAddress(&pkh, g_Kh);
    cudaGetSymbolAddress(&pvt, g_VTh);
    float* Q = (float*)pq;
    float* K = (float*)pk;
    float* V = (float*)pv;
    __half* Xh = (__half*)pxh;
    __half* Xl = (__half*)pxl;
    __half* Wh = (__half*)pwh;

    cudaFuncSetAttribute(gemm_mma, cudaFuncAttributeMaxDynamicSharedMemorySize, GM_SMEM);
    cudaFuncSetAttribute(flash_mma, cudaFuncAttributeMaxDynamicSharedMemorySize, FM_SMEM);

    const int M = 4096, D = 2048;
    const int nX4 = M * D / 4;
    const int nW4 = D * D / 4;
    dim3 gg(D / 128, M / 128);      // (16, 32)

    split_h2<<<(nX4 + 255) / 256, 256>>>(x, Xh, Xl, nX4, 1.0f);

    conv_h<<<(nW4 + 255) / 256, 256>>>(wq, Wh, nW4);
    gemm_mma<<<gg, 256, GM_SMEM>>>(Xh, Xl, Wh, Q);

    conv_h<<<(nW4 + 255) / 256, 256>>>(wk, Wh, nW4);
    gemm_mma<<<gg, 256, GM_SMEM>>>(Xh, Xl, Wh, K);

    conv_h<<<(nW4 + 255) / 256, 256>>>(wv, Wh, nW4);
    gemm_mma<<<gg, 256, GM_SMEM>>>(Xh, Xl, Wh, V);

    // fused rmsnorm (+ qscale = 1/sqrt(128) * log2(e) on Q)
    const float qscale = 0.08838834764831845f * 1.4426950408889634f;
    int nrows = M * 16;
    rmsnorm_split_h2<<<nrows / 8, 256>>>(Q, qn, (__half*)pqh, (__half*)pql,
                                         nrows, qscale);
    rmsnorm_h<<<nrows / 8, 256>>>(K, kn, (__half*)pkh, nrows);
    transpose_h<<<dim3(M / 32, D / 32), 256>>>(V, (__half*)pvt);

    // flash writes fp16 hi/lo into Xh/Xl (A operand of O-proj)
    flash_mma<<<dim3(M / 128, 16), 256, FM_SMEM>>>(
        (__half*)pqh, (__half*)pql, (__half*)pkh, (__half*)pvt, Xh, Xl);

    conv_h<<<(nW4 + 255) / 256, 256>>>(wo, Wh, nW4);
    gemm_mma<<<gg, 256, GM_SMEM>>>(Xh, Xl, Wh, out);
}

// round 11
// speedup vs baseline: 4.2267x; 1.5289x over previous
#include <cuda_runtime.h>
#include <cuda_fp16.h>
#include <cstdint>
#include <math.h>

// ---------------- scratch (static device globals; no allocation) ----------
__device__ float g_Q[4096 * 2048];
__device__ float g_K[4096 * 2048];
__device__ float g_V[4096 * 2048];
__device__ __half g_Xh[4096 * 2048];     // x fp16; later attention-out fp16
__device__ __half g_Wh[2048 * 2048];     // weight fp16
__device__ __half g_Qh[4096 * 2048];
__device__ __half g_Kh[4096 * 2048];
__device__ __half g_VTh[2048 * 4096];    // [h*128+d][s], fp16

// ======================= portable PTX helpers (sm_80+) =====================
__device__ __forceinline__ uint32_t smem_u32(const void* p) {
    uint32_t a;
    asm("{ .reg .u64 t; cvta.to.shared.u64 t, %1; cvt.u32.u64 %0, t; }"
        : "=r"(a) : "l"(p));
    return a;
}
#define CP_ASYNC16(dst, src) \
    asm volatile("cp.async.cg.shared.global [%0], [%1], 16;" \
                 :: "r"(dst), "l"(src))
#define CP_COMMIT() asm volatile("cp.async.commit_group;")
#define CP_WAIT1()  asm volatile("cp.async.wait_group 1;")
#define CP_WAIT0()  asm volatile("cp.async.wait_group 0;")
#define LDSM_X4(r, addr) \
    asm volatile("ldmatrix.sync.aligned.m8n8.x4.shared.b16 {%0,%1,%2,%3}, [%4];" \
                 : "=r"((r)[0]), "=r"((r)[1]), "=r"((r)[2]), "=r"((r)[3]) \
                 : "r"(addr))
#define MMAF16(d, a, b0, b1) \
    asm volatile("mma.sync.aligned.m16n8k16.row.col.f32.f16.f16.f32 " \
                 "{%0,%1,%2,%3}, {%4,%5,%6,%7}, {%8,%9}, {%0,%1,%2,%3};" \
                 : "+f"((d)[0]), "+f"((d)[1]), "+f"((d)[2]), "+f"((d)[3]) \
                 : "r"((a)[0]), "r"((a)[1]), "r"((a)[2]), "r"((a)[3]), \
                   "r"(b0), "r"(b1))
__device__ __forceinline__ float ex2(float x) {
    float r;
    asm("ex2.approx.f32 %0, %1;" : "=f"(r) : "f"(x));
    return r;
}

// ---------------------------------------------------------------------------
// convert fp32 -> fp16
// ---------------------------------------------------------------------------
__global__ void __launch_bounds__(256) conv_h(const float* __restrict__ in,
                                              __half* __restrict__ out, int n4) {
    int i = blockIdx.x * blockDim.x + threadIdx.x;
    if (i >= n4) return;
    float4 v = ((const float4*)in)[i];
    union { __half b[4]; uint2 u; } H;
    H.b[0] = __float2half_rn(v.x);
    H.b[1] = __float2half_rn(v.y);
    H.b[2] = __float2half_rn(v.z);
    H.b[3] = __float2half_rn(v.w);
    ((uint2*)out)[i] = H.u;
}

// ---------------------------------------------------------------------------
// fused rmsnorm + scale + fp16 convert (one warp / (token,head) row)
// ---------------------------------------------------------------------------
__global__ void __launch_bounds__(256) rmsnorm_h(
    const float* __restrict__ X, const float* __restrict__ w,
    __half* __restrict__ out, int nrows, float scale) {
    int warp = (blockIdx.x * blockDim.x + threadIdx.x) >> 5;
    int lane = threadIdx.x & 31;
    if (warp >= nrows) return;

    float4 v = *(const float4*)&X[(size_t)warp * 128 + (lane << 2)];
    float ss = v.x * v.x + v.y * v.y + v.z * v.z + v.w * v.w;
#pragma unroll
    for (int off = 16; off > 0; off >>= 1)
        ss += __shfl_xor_sync(0xffffffffu, ss, off);

    float inv = rsqrtf(ss * (1.0f / 128.0f) + 1e-6f) * scale;
    float4 wv = *(const float4*)&w[lane << 2];
    union { __half b[4]; uint2 u; } H;
    H.b[0] = __float2half_rn(v.x * inv * wv.x);
    H.b[1] = __float2half_rn(v.y * inv * wv.y);
    H.b[2] = __float2half_rn(v.z * inv * wv.z);
    H.b[3] = __float2half_rn(v.w * inv * wv.w);
    ((uint2*)out)[(size_t)warp * 32 + lane] = H.u;
}

// ---------------------------------------------------------------------------
// transpose + fp16 convert V: [4096][2048] fp32 -> VT [2048][4096] fp16
// ---------------------------------------------------------------------------
__global__ void __launch_bounds__(256) transpose_h(
    const float* __restrict__ in, __half* __restrict__ th) {
    __shared__ float t[32][33];
    const int s0 = blockIdx.x << 5;
    const int c0 = blockIdx.y << 5;
    const int tx = threadIdx.x & 31;
    const int ty = threadIdx.x >> 5;
#pragma unroll
    for (int i = 0; i < 4; i++) {
        int r = (ty << 2) + i;
        t[r][tx] = in[(size_t)(s0 + r) * 2048 + c0 + tx];
    }
    __syncthreads();
#pragma unroll
    for (int i = 0; i < 4; i++) {
        int r = (ty << 2) + i;
        th[(size_t)(c0 + r) * 4096 + s0 + tx] = __float2half_rn(t[tx][r]);
    }
}

// ---------------------------------------------------------------------------
// gemm fp16 1-pass:  C = Ah * Bh^T
// CTA 128x128, 8 warps (warp 64x32), K chunk 32 (64B rows), 3-stage cp.async,
// 1 sync/iter, NITER=64. Stage = Ah|Bh (16KB).
// ---------------------------------------------------------------------------
#define GMS      16384              // stage: 2 tiles x 8KB
#define GM_SMEM  (3 * GMS)          // 49152

__global__ void __launch_bounds__(256, 2) gemm_mma(
    const __half* __restrict__ Ah, const __half* __restrict__ Bh,
    float* __restrict__ C) {
    constexpr int Nd = 2048, Kd = 2048;
    extern __shared__ char smem[];
    const uint32_t sbase = smem_u32(smem);
    const int tid = threadIdx.x;
    const int lane = tid & 31;
    const int wid = tid >> 5;
    const int m0 = blockIdx.y << 7;
    const int n0 = blockIdx.x << 7;
    const int wm = (wid & 1) << 6;       // 0/64
    const int wn = (wid >> 1) << 5;      // 0/32/64/96

    float acc[4][4][4];
#pragma unroll
    for (int mi = 0; mi < 4; mi++)
#pragma unroll
        for (int ni = 0; ni < 4; ni++)
#pragma unroll
            for (int q = 0; q < 4; q++) acc[mi][ni][q] = 0.f;

    const int lr = tid >> 1;             // row 0..127
    const int lc0 = (tid & 1) << 1;      // chunk 0 or 2

    auto issue = [&](int it, int stage) {
        int kk = it << 5;
        const __half* pAh = Ah + (size_t)(m0 + lr) * Kd + kk;
        const __half* pBh = Bh + (size_t)(n0 + lr) * Kd + kk;
        uint32_t st = sbase + stage * GMS + lr * 64;
#pragma unroll
        for (int j = 0; j < 2; j++) {
            int c = lc0 + j;
            uint32_t sw = (uint32_t)((c ^ ((lr >> 1) & 3)) << 4);
            CP_ASYNC16(st + sw,        pAh + c * 8);
            CP_ASYNC16(st + 8192 + sw, pBh + c * 8);
        }
    };

    issue(0, 0); CP_COMMIT();
    issue(1, 1); CP_COMMIT();

    constexpr int NITER = 64;            // 2048 / 32
    int stage = 0, nstage = 2;
    for (int it = 0; it < NITER; it++) {
        if (it < NITER - 1) CP_WAIT1(); else CP_WAIT0();
        __syncthreads();
        if (it + 2 < NITER) { issue(it + 2, nstage); CP_COMMIT(); }

        const uint32_t sAh = sbase + stage * GMS;
        const uint32_t sBh = sAh + 8192;

#pragma unroll
        for (int ks = 0; ks < 2; ks++) {
            uint32_t bh[2][4];
#pragma unroll
            for (int pr = 0; pr < 2; pr++) {
                int row = wn + pr * 16 + (lane & 7) + (((lane >> 4) & 1) << 3);
                int c = ks * 2 + ((lane >> 3) & 1);
                uint32_t off = (uint32_t)(row * 64 + ((c ^ ((row >> 1) & 3)) << 4));
                LDSM_X4(bh[pr], sBh + off);
            }
#pragma unroll
            for (int mi = 0; mi < 4; mi++) {
                uint32_t ah[4];
                int row = wm + mi * 16 + (lane & 15);
                int c = ks * 2 + (lane >> 4);
                uint32_t off = (uint32_t)(row * 64 + ((c ^ ((row >> 1) & 3)) << 4));
                LDSM_X4(ah, sAh + off);
#pragma unroll
                for (int ni = 0; ni < 4; ni++)
                    MMAF16(acc[mi][ni], ah,
                           bh[ni >> 1][(ni & 1) << 1],
                           bh[ni >> 1][((ni & 1) << 1) + 1]);
            }
        }
        stage = (stage == 2) ? 0 : stage + 1;
        nstage = (nstage == 2) ? 0 : nstage + 1;
    }

    // epilogue
#pragma unroll
    for (int mi = 0; mi < 4; mi++) {
        int r0 = m0 + wm + mi * 16 + (lane >> 2);
#pragma unroll
        for (int ni = 0; ni < 4; ni++) {
            int cc = n0 + wn + ni * 8 + ((lane & 3) << 1);
            *(float2*)&C[(size_t)r0 * Nd + cc] =
                make_float2(acc[mi][ni][0], acc[mi][ni][1]);
            *(float2*)&C[(size_t)(r0 + 8) * Nd + cc] =
                make_float2(acc[mi][ni][2], acc[mi][ni][3]);
        }
    }
}

// ---------------------------------------------------------------------------
// Flash attention fp16 1-pass: S = Qh*Kh^T ; O = Ph*Vh.
// 128 queries x one head per CTA, 8 warps. K tiles of 64, 2-stage cp.async.
// Epilogue writes fp16 O directly (A operand of O-projection).
// ---------------------------------------------------------------------------
#define FM_QH    0
#define FM_STG0  32768
#define FM_STAGE 32768               // Kh 16KB | Vh 16KB
#define FM_SMEM  (32768 + 2 * FM_STAGE)   // 98304

__device__ __forceinline__ uint32_t sw256(int row, int kb) {
    return (uint32_t)(row * 256 + ((kb & 0x80) | ((kb ^ ((row & 7) << 4)) & 0x70)));
}

__global__ void __launch_bounds__(256, 1) flash_mma(
    const __half* __restrict__ Qh, const __half* __restrict__ Kh,
    const __half* __restrict__ VTh, __half* __restrict__ Oh) {
    extern __shared__ char smem[];
    const uint32_t sb = smem_u32(smem);
    const int tid = threadIdx.x;
    const int lane = tid & 31;
    const int wid = tid >> 5;
    const int h = blockIdx.y;
    const int m0 = blockIdx.x << 7;
    const int hoff = h << 7;
    const int qbase = wid << 4;

    // ---- load Q tile ----
    {
        int row = tid >> 1;
        int c0 = (tid & 1) << 3;
        const __half* qh = Qh + (size_t)(m0 + row) * 2048 + hoff;
#pragma unroll
        for (int j = 0; j < 8; j++) {
            int c = c0 + j;
            CP_ASYNC16(sb + FM_QH + sw256(row, c << 4), qh + c * 8);
        }
    }

    const int krow = tid >> 2;           // 0..63
    const int kc0 = (tid & 3) << 2;
    const int vrow = tid >> 1;           // 0..127
    const int vc0 = (tid & 1) << 2;

#define FM_ISSUE(kt, buf) do {                                                  \
    uint32_t _st = sb + FM_STG0 + (buf) * FM_STAGE;                             \
    const __half* _kh = Kh + (size_t)((kt) + krow) * 2048 + hoff;               \
    _Pragma("unroll")                                                           \
    for (int _j = 0; _j < 4; _j++) {                                            \
        int _c = kc0 + _j;                                                      \
        CP_ASYNC16(_st + sw256(krow, _c << 4), _kh + _c * 8);                   \
    }                                                                           \
    const __half* _vh = VTh + (size_t)(hoff + vrow) * 4096 + (kt);              \
    _Pragma("unroll")                                                           \
    for (int _j = 0; _j < 4; _j++) {                                            \
        int _c = vc0 + _j;                                                      \
        uint32_t _sw = (uint32_t)(vrow * 128 + ((_c << 4) ^ ((vrow & 7) << 4)));\
        CP_ASYNC16(_st + 16384 + _sw, _vh + _c * 8);                            \
    }                                                                           \
} while (0)

    FM_ISSUE(0, 0);
    CP_COMMIT();

    float m0s = -1e30f, m1s = -1e30f, l0 = 0.f, l1 = 0.f;
    float o[16][4];
#pragma unroll
    for (int j = 0; j < 16; j++)
#pragma unroll
        for (int q = 0; q < 4; q++) o[j][q] = 0.f;

    const int NITER = 4096 / 64;
    for (int it = 0; it < NITER; it++) {
        const int buf = it & 1;
        CP_WAIT0();
        __syncthreads();
        if (it + 1 < NITER) {
            FM_ISSUE((it + 1) << 6, buf ^ 1);
            CP_COMMIT();
        }

        const uint32_t sKh = sb + FM_STG0 + buf * FM_STAGE;
        const uint32_t sVh = sKh + 16384;

        // ---- S = Q K^T ----
        float s[8][4];
#pragma unroll
        for (int j = 0; j < 8; j++)
#pragma unroll
            for (int q = 0; q < 4; q++) s[j][q] = 0.f;

#pragma unroll
        for (int ks = 0; ks < 8; ks++) {
            uint32_t ah[4], bh[4][4];
            {
                int row = qbase + (lane & 15);
                int kb = ks * 32 + ((lane >> 4) << 4);
                LDSM_X4(ah, sb + FM_QH + sw256(row, kb));
            }
#pragma unroll
            for (int pr = 0; pr < 4; pr++) {
                int row = pr * 16 + (lane & 7) + (((lane >> 4) & 1) << 3);
                int kb = ks * 32 + (((lane >> 3) & 1) << 4);
                LDSM_X4(bh[pr], sKh + sw256(row, kb));
            }
#pragma unroll
            for (int j = 0; j < 8; j++)
                MMAF16(s[j], ah, bh[j >> 1][(j & 1) << 1],
                       bh[j >> 1][((j & 1) << 1) + 1]);
        }

        // ---- online softmax (base-2) ----
        float mx0 = -1e30f, mx1 = -1e30f;
#pragma unroll
        for (int j = 0; j < 8; j++) {
            mx0 = fmaxf(mx0, fmaxf(s[j][0], s[j][1]));
            mx1 = fmaxf(mx1, fmaxf(s[j][2], s[j][3]));
        }
        mx0 = fmaxf(mx0, __shfl_xor_sync(0xffffffffu, mx0, 1));
        mx0 = fmaxf(mx0, __shfl_xor_sync(0xffffffffu, mx0, 2));
        mx1 = fmaxf(mx1, __shfl_xor_sync(0xffffffffu, mx1, 1));
        mx1 = fmaxf(mx1, __shfl_xor_sync(0xffffffffu, mx1, 2));
        float mn0 = fmaxf(m0s, mx0), mn1 = fmaxf(m1s, mx1);
        float corr0 = ex2(m0s - mn0), corr1 = ex2(m1s - mn1);
        m0s = mn0; m1s = mn1;

        float sum0 = 0.f, sum1 = 0.f;
        float p[8][4];
#pragma unroll
        for (int j = 0; j < 8; j++) {
            p[j][0] = ex2(s[j][0] - mn0);
            p[j][1] = ex2(s[j][1] - mn0);
            p[j][2] = ex2(s[j][2] - mn1);
            p[j][3] = ex2(s[j][3] - mn1);
            sum0 += p[j][0] + p[j][1];
            sum1 += p[j][2] + p[j][3];
        }
        sum0 += __shfl_xor_sync(0xffffffffu, sum0, 1);
        sum0 += __shfl_xor_sync(0xffffffffu, sum0, 2);
        sum1 += __shfl_xor_sync(0xffffffffu, sum1, 1);
        sum1 += __shfl_xor_sync(0xffffffffu, sum1, 2);
        l0 = l0 * corr0 + sum0;
        l1 = l1 * corr1 + sum1;

        // pack P -> fp16 A-fragments
        uint32_t pa[4][4];
#pragma unroll
        for (int kt = 0; kt < 4; kt++) {
#pragma unroll
            for (int t = 0; t < 2; t++) {
                int j = 2 * kt + t;
#pragma unroll
                for (int half = 0; half < 2; half++) {
                    __half2 hh = __floats2half2_rn(p[j][half * 2],
                                                   p[j][half * 2 + 1]);
                    pa[kt][t * 2 + half] = *(uint32_t*)&hh;
                }
            }
        }

#pragma unroll
        for (int j = 0; j < 16; j++) {
            o[j][0] *= corr0; o[j][1] *= corr0;
            o[j][2] *= corr1; o[j][3] *= corr1;
        }

        // ---- O += P V ----
#pragma unroll
        for (int kt = 0; kt < 4; kt++) {
#pragma unroll
            for (int prp = 0; prp < 4; prp++) {
                uint32_t bvh[2][4];
#pragma unroll
                for (int e = 0; e < 2; e++) {
                    int pr = prp * 2 + e;
                    int row = pr * 16 + (lane & 7) + (((lane >> 4) & 1) << 3);
                    int kb = kt * 32 + (((lane >> 3) & 1) << 4);
                    uint32_t sw = (uint32_t)(row * 128 + (kb ^ ((row & 7) << 4)));
                    LDSM_X4(bvh[e], sVh + sw);
                }
#pragma unroll
                for (int q = 0; q < 4; q++)
                    MMAF16(o[prp * 4 + q], pa[kt],
                           bvh[q >> 1][(q & 1) << 1],
                           bvh[q >> 1][((q & 1) << 1) + 1]);
            }
        }
    }

    // ---- epilogue: write fp16 O (A operand of O-proj) ----
    // acc j = prp*4 + e*2 + t where pr = prp*2+e; output ntile = pr*2+t
    float inv0 = 1.0f / l0, inv1 = 1.0f / l1;
    int r0 = m0 + qbase + (lane >> 2);
#pragma unroll
    for (int j = 0; j < 16; j++) {
        int prp = j >> 2, e = (j >> 1) & 1, t = j & 1;
        int ntile = (prp * 2 + e) * 2 + t;
        int cc = hoff + ntile * 8 + ((lane & 3) << 1);
        {
            __half2 hh = __floats2half2_rn(o[j][0] * inv0, o[j][1] * inv0);
            *(uint32_t*)&Oh[(size_t)r0 * 2048 + cc] = *(uint32_t*)&hh;
        }
        {
            __half2 hh = __floats2half2_rn(o[j][2] * inv1, o[j][3] * inv1);
            *(uint32_t*)&Oh[(size_t)(r0 + 8) * 2048 + cc] = *(uint32_t*)&hh;
        }
    }
}

// ---------------------------------------------------------------------------
// Launch
// ---------------------------------------------------------------------------
extern "C" void kernel_launch(void* const* d_in, const int* in_sizes, int n_in,
                              void* d_out, int out_size) {
    const float* x  = (const float*)d_in[0];
    const float* wq = (const float*)d_in[1];
    const float* wk = (const float*)d_in[2];
    const float* wv = (const float*)d_in[3];
    const float* wo = (const float*)d_in[4];
    const float* qn = (const float*)d_in[5];
    const float* kn = (const float*)d_in[6];
    float* out = (float*)d_out;

    void *pq, *pk, *pv, *pxh, *pwh, *pqh, *pkh, *pvt;
    cudaGetSymbolAddress(&pq, g_Q);
    cudaGetSymbolAddress(&pk, g_K);
    cudaGetSymbolAddress(&pv, g_V);
    cudaGetSymbolAddress(&pxh, g_Xh);
    cudaGetSymbolAddress(&pwh, g_Wh);
    cudaGetSymbolAddress(&pqh, g_Qh);
    cudaGetSymbolAddress(&pkh, g_Kh);
    cudaGetSymbolAddress(&pvt, g_VTh);
    float* Q = (float*)pq;
    float* K = (float*)pk;
    float* V = (float*)pv;
    __half* Xh = (__half*)pxh;
    __half* Wh = (__half*)pwh;

    cudaFuncSetAttribute(gemm_mma, cudaFuncAttributeMaxDynamicSharedMemorySize, GM_SMEM);
    cudaFuncSetAttribute(flash_mma, cudaFuncAttributeMaxDynamicSharedMemorySize, FM_SMEM);

    const int M = 4096, D = 2048;
    const int nX4 = M * D / 4;
    const int nW4 = D * D / 4;
    dim3 gg(D / 128, M / 128);      // (16, 32)

    conv_h<<<(nX4 + 255) / 256, 256>>>(x, Xh, nX4);

    conv_h<<<(nW4 + 255) / 256, 256>>>(wq, Wh, nW4);
    gemm_mma<<<gg, 256, GM_SMEM>>>(Xh, Wh, Q);

    conv_h<<<(nW4 + 255) / 256, 256>>>(wk, Wh, nW4);
    gemm_mma<<<gg, 256, GM_SMEM>>>(Xh, Wh, K);

    conv_h<<<(nW4 + 255) / 256, 256>>>(wv, Wh, nW4);
    gemm_mma<<<gg, 256, GM_SMEM>>>(Xh, Wh, V);

    // fused rmsnorm (+ qscale = 1/sqrt(128) * log2(e) on Q)
    const float qscale = 0.08838834764831845f * 1.4426950408889634f;
    int nrows = M * 16;
    rmsnorm_h<<<nrows / 8, 256>>>(Q, qn, (__half*)pqh, nrows, qscale);
    rmsnorm_h<<<nrows / 8, 256>>>(K, kn, (__half*)pkh, nrows, 1.0f);
    transpose_h<<<dim3(M / 32, D / 32), 256>>>(V, (__half*)pvt);

    // flash writes fp16 O into Xh (A operand of O-proj)
    flash_mma<<<dim3(M / 128, 16), 256, FM_SMEM>>>(
        (__half*)pqh, (__half*)pkh, (__half*)pvt, Xh);

    conv_h<<<(nW4 + 255) / 256, 256>>>(wo, Wh, nW4);
    gemm_mma<<<gg, 256, GM_SMEM>>>(Xh, Wh, out);
}